// round 3
// baseline (speedup 1.0000x reference)
#include <cuda_runtime.h>

// ---------------------------------------------------------------------------
// MultiHeadAttention: B=2, S=2048, D_MODEL=1024, H=16, DEPTH=64
// d_out = [ out (B,S,D) | attn (B,H,S,S) ]
// ---------------------------------------------------------------------------

namespace {
constexpr int Bc = 2;
constexpr int Sc = 2048;
constexpr int DM = 1024;
constexpr int Hc = 16;
constexpr int DEPTH = 64;
constexpr int BH = Bc * Hc;        // 32
constexpr int MROWS = Bc * Sc;     // 4096
constexpr float SCALE = 0.125f;    // 1/sqrt(64)
constexpr float NEG_BIG = -3.0e38f;
}

__device__ float g_qh[BH * Sc * DEPTH];   // (B,H,S,64)
__device__ float g_kh[BH * Sc * DEPTH];
__device__ float g_vh[BH * Sc * DEPTH];
__device__ float g_ctx[MROWS * DM];       // context, merged-head row-major
__device__ float g_m[BH * Sc];
__device__ float g_s[BH * Sc];

__device__ __forceinline__ float rmax16(float v) {
#pragma unroll
    for (int o = 8; o > 0; o >>= 1)
        v = fmaxf(v, __shfl_xor_sync(0xffffffffu, v, o));
    return v;
}
__device__ __forceinline__ float rsum16(float v) {
#pragma unroll
    for (int o = 8; o > 0; o >>= 1)
        v += __shfl_xor_sync(0xffffffffu, v, o);
    return v;
}

// ---------------------------------------------------------------------------
// Fused QKV projection. Tile 128(M) x 64(N) x 16(K), 256 thr, 8x4/thread.
// blockIdx.z selects q/k/v. Output written head-split.
// ---------------------------------------------------------------------------
__global__ __launch_bounds__(256) void qkv_proj_kernel(
    const float* __restrict__ q, const float* __restrict__ k,
    const float* __restrict__ v,
    const float* __restrict__ wq, const float* __restrict__ wk,
    const float* __restrict__ wv,
    const float* __restrict__ bq, const float* __restrict__ bk,
    const float* __restrict__ bv) {
    const int sel = blockIdx.z;
    const float* X = (sel == 0) ? q : ((sel == 1) ? k : v);
    const float* W = (sel == 0) ? wq : ((sel == 1) ? wk : wv);
    const float* bias = (sel == 0) ? bq : ((sel == 1) ? bk : bv);
    float* out = (sel == 0) ? g_qh : ((sel == 1) ? g_kh : g_vh);

    __shared__ float As[128][20];   // [m][k], pad 4 (80B rows, 16B aligned)
    __shared__ float Bs[16][68];    // [k][n], pad 4

    const int tid = threadIdx.x;
    const int tx = tid & 15;        // 4 cols each
    const int ty = tid >> 4;        // 8 rows each
    const int m0 = blockIdx.y * 128;
    const int n0 = blockIdx.x * 64;

    float acc[8][4];
#pragma unroll
    for (int i = 0; i < 8; i++)
#pragma unroll
        for (int j = 0; j < 4; j++) acc[i][j] = 0.0f;

    for (int k0 = 0; k0 < DM; k0 += 16) {
#pragma unroll
        for (int i = 0; i < 2; i++) {
            int e = tid + i * 256;
            int r = e >> 2, c4 = e & 3;
            float4 f = *(const float4*)&X[(size_t)(m0 + r) * DM + k0 + c4 * 4];
            *(float4*)&As[r][c4 * 4] = f;
        }
        {
            int r = tid >> 4, c4 = tid & 15;
            float4 f = *(const float4*)&W[(size_t)(k0 + r) * DM + n0 + c4 * 4];
            *(float4*)&Bs[r][c4 * 4] = f;
        }
        __syncthreads();
#pragma unroll
        for (int kk = 0; kk < 16; kk++) {
            float a[8];
#pragma unroll
            for (int i = 0; i < 8; i++) a[i] = As[ty * 8 + i][kk];
            float4 bv4 = *(const float4*)&Bs[kk][tx * 4];
#pragma unroll
            for (int i = 0; i < 8; i++) {
                acc[i][0] = fmaf(a[i], bv4.x, acc[i][0]);
                acc[i][1] = fmaf(a[i], bv4.y, acc[i][1]);
                acc[i][2] = fmaf(a[i], bv4.z, acc[i][2]);
                acc[i][3] = fmaf(a[i], bv4.w, acc[i][3]);
            }
        }
        __syncthreads();
    }

    const int h = n0 >> 6;                 // n0 is a multiple of 64
    float4 bb = *(const float4*)&bias[n0 + tx * 4];
#pragma unroll
    for (int i = 0; i < 8; i++) {
        int row = m0 + ty * 8 + i;
        int b = row >> 11, s = row & 2047;
        float4 o;
        o.x = acc[i][0] + bb.x;
        o.y = acc[i][1] + bb.y;
        o.z = acc[i][2] + bb.z;
        o.w = acc[i][3] + bb.w;
        *(float4*)&out[(((size_t)(b * Hc + h)) * Sc + s) * DEPTH + tx * 4] = o;
    }
}

// ---------------------------------------------------------------------------
// Pass 1: raw scaled logits -> attn region, online (max, sumexp) per row.
// Block: 128 q-rows x all k (16 tiles of 128). 8x8 per thread.
// ---------------------------------------------------------------------------
__global__ __launch_bounds__(256, 2) void logits_kernel(float* __restrict__ attn) {
    extern __shared__ float sm[];
    float (*Qs)[68] = (float(*)[68])sm;                 // 128 x 68 (q-major)
    float (*Kt)[132] = (float(*)[132])(sm + 128 * 68);  // 64 x 132 (d-major)

    const int bh = blockIdx.y;
    const int q0 = blockIdx.x * 128;
    const int tid = threadIdx.x;
    const int tx = tid & 15;    // 8 k-cols each
    const int ty = tid >> 4;    // 8 q-rows each

    const float* Qb = g_qh + (size_t)bh * Sc * DEPTH;
    const float* Kb = g_kh + (size_t)bh * Sc * DEPTH;

    // load Q tile (128 x 64), natural layout
#pragma unroll
    for (int i = 0; i < 8; i++) {
        int e = tid + i * 256;
        int r = e >> 4, c4 = e & 15;
        float4 f = *(const float4*)&Qb[(size_t)(q0 + r) * DEPTH + c4 * 4];
        *(float4*)&Qs[r][c4 * 4] = f;
    }

    float m_run[8], s_run[8];
#pragma unroll
    for (int i = 0; i < 8; i++) { m_run[i] = NEG_BIG; s_run[i] = 0.0f; }

    for (int k0 = 0; k0 < Sc; k0 += 128) {
        __syncthreads();
        // load K tile (128 k x 64 d) transposed -> Kt[d][k]
#pragma unroll
        for (int i = 0; i < 8; i++) {
            int e = tid + i * 256;
            int r = e >> 4, c4 = e & 15;
            float4 f = *(const float4*)&Kb[(size_t)(k0 + r) * DEPTH + c4 * 4];
            Kt[c4 * 4 + 0][r] = f.x;
            Kt[c4 * 4 + 1][r] = f.y;
            Kt[c4 * 4 + 2][r] = f.z;
            Kt[c4 * 4 + 3][r] = f.w;
        }
        __syncthreads();

        float l[8][8];
#pragma unroll
        for (int i = 0; i < 8; i++)
#pragma unroll
            for (int j = 0; j < 8; j++) l[i][j] = 0.0f;

#pragma unroll 16
        for (int d = 0; d < 64; d++) {
            float a[8];
#pragma unroll
            for (int i = 0; i < 8; i++) a[i] = Qs[ty * 8 + i][d];
            float4 b0 = *(const float4*)&Kt[d][tx * 8];
            float4 b1 = *(const float4*)&Kt[d][tx * 8 + 4];
#pragma unroll
            for (int i = 0; i < 8; i++) {
                l[i][0] = fmaf(a[i], b0.x, l[i][0]);
                l[i][1] = fmaf(a[i], b0.y, l[i][1]);
                l[i][2] = fmaf(a[i], b0.z, l[i][2]);
                l[i][3] = fmaf(a[i], b0.w, l[i][3]);
                l[i][4] = fmaf(a[i], b1.x, l[i][4]);
                l[i][5] = fmaf(a[i], b1.y, l[i][5]);
                l[i][6] = fmaf(a[i], b1.z, l[i][6]);
                l[i][7] = fmaf(a[i], b1.w, l[i][7]);
            }
        }

#pragma unroll
        for (int i = 0; i < 8; i++) {
            int row = q0 + ty * 8 + i;
            float* arow = attn + ((size_t)bh * Sc + row) * Sc + k0 + tx * 8;
            float tmax = NEG_BIG;
#pragma unroll
            for (int j = 0; j < 8; j++) {
                l[i][j] *= SCALE;
                tmax = fmaxf(tmax, l[i][j]);
            }
            float4 s0 = make_float4(l[i][0], l[i][1], l[i][2], l[i][3]);
            float4 s1 = make_float4(l[i][4], l[i][5], l[i][6], l[i][7]);
            *(float4*)&arow[0] = s0;
            *(float4*)&arow[4] = s1;
            tmax = rmax16(tmax);
            float mnew = fmaxf(m_run[i], tmax);
            float ps = 0.0f;
#pragma unroll
            for (int j = 0; j < 8; j++) ps += __expf(l[i][j] - mnew);
            ps = rsum16(ps);
            s_run[i] = s_run[i] * __expf(m_run[i] - mnew) + ps;
            m_run[i] = mnew;
        }
    }

    if (tx == 0) {
#pragma unroll
        for (int i = 0; i < 8; i++) {
            int row = q0 + ty * 8 + i;
            g_m[bh * Sc + row] = m_run[i];
            g_s[bh * Sc + row] = s_run[i];
        }
    }
}

// ---------------------------------------------------------------------------
// Pass 2: normalize attn in place + ctx = attn @ V (merged-head layout).
// Block: 128 q-rows x 64 d, k in chunks of 64. 4x8 per thread.
// ---------------------------------------------------------------------------
__global__ __launch_bounds__(256) void av_kernel(float* __restrict__ attn) {
    extern __shared__ float sm[];
    float (*Ps)[68] = (float(*)[68])sm;                // 128 x 68
    float (*Vs)[68] = (float(*)[68])(sm + 128 * 68);   // 64 x 68
    float* msm = sm + 128 * 68 + 64 * 68;              // 128
    float* ssm = msm + 128;                            // 128 (1/sum)

    const int bh = blockIdx.y;
    const int q0 = blockIdx.x * 128;
    const int tid = threadIdx.x;
    const int tx = tid & 7;     // 8 d-cols each
    const int ty = tid >> 3;    // 4 q-rows each

    const float* Vb = g_vh + (size_t)bh * Sc * DEPTH;

    if (tid < 128) {
        msm[tid] = g_m[bh * Sc + q0 + tid];
        ssm[tid] = 1.0f / g_s[bh * Sc + q0 + tid];
    }

    float acc[4][8];
#pragma unroll
    for (int i = 0; i < 4; i++)
#pragma unroll
        for (int j = 0; j < 8; j++) acc[i][j] = 0.0f;

    for (int k0 = 0; k0 < Sc; k0 += 64) {
        __syncthreads();
        // V tile 64 x 64
#pragma unroll
        for (int i = 0; i < 4; i++) {
            int e = tid + i * 256;
            int r = e >> 4, c4 = e & 15;
            float4 f = *(const float4*)&Vb[(size_t)(k0 + r) * DEPTH + c4 * 4];
            *(float4*)&Vs[r][c4 * 4] = f;
        }
        // P chunk 128 q x 64 k: read raw logits, exp-normalize, write back + smem
#pragma unroll
        for (int i = 0; i < 8; i++) {
            int e = tid + i * 256;
            int r = e >> 4, c4 = e & 15;
            float* gp = attn + ((size_t)bh * Sc + q0 + r) * Sc + k0 + c4 * 4;
            float4 x = *(const float4*)gp;
            float mm = msm[r], si = ssm[r];
            float4 p;
            p.x = __expf(x.x - mm) * si;
            p.y = __expf(x.y - mm) * si;
            p.z = __expf(x.z - mm) * si;
            p.w = __expf(x.w - mm) * si;
            *(float4*)gp = p;
            *(float4*)&Ps[r][c4 * 4] = p;
        }
        __syncthreads();

#pragma unroll 16
        for (int kk = 0; kk < 64; kk++) {
            float a[4];
#pragma unroll
            for (int i = 0; i < 4; i++) a[i] = Ps[ty * 4 + i][kk];
            float4 b0 = *(const float4*)&Vs[kk][tx * 8];
            float4 b1 = *(const float4*)&Vs[kk][tx * 8 + 4];
#pragma unroll
            for (int i = 0; i < 4; i++) {
                acc[i][0] = fmaf(a[i], b0.x, acc[i][0]);
                acc[i][1] = fmaf(a[i], b0.y, acc[i][1]);
                acc[i][2] = fmaf(a[i], b0.z, acc[i][2]);
                acc[i][3] = fmaf(a[i], b0.w, acc[i][3]);
                acc[i][4] = fmaf(a[i], b1.x, acc[i][4]);
                acc[i][5] = fmaf(a[i], b1.y, acc[i][5]);
                acc[i][6] = fmaf(a[i], b1.z, acc[i][6]);
                acc[i][7] = fmaf(a[i], b1.w, acc[i][7]);
            }
        }
    }

    // store ctx in merged layout: [(b*S+s)*DM + h*64 + d]
    const int b = bh >> 4, h = bh & 15;
#pragma unroll
    for (int i = 0; i < 4; i++) {
        int s = q0 + ty * 4 + i;
        float* cp = g_ctx + ((size_t)(b * Sc + s)) * DM + h * 64 + tx * 8;
        *(float4*)&cp[0] = make_float4(acc[i][0], acc[i][1], acc[i][2], acc[i][3]);
        *(float4*)&cp[4] = make_float4(acc[i][4], acc[i][5], acc[i][6], acc[i][7]);
    }
}

// ---------------------------------------------------------------------------
// Output projection: out = ctx @ wo + bo. Tile 128x64x16, 8x4/thread.
// ---------------------------------------------------------------------------
__global__ __launch_bounds__(256) void out_proj_kernel(
    const float* __restrict__ WO, const float* __restrict__ bo,
    float* __restrict__ out) {
    __shared__ float As[128][20];
    __shared__ float Bs[16][68];

    const int tid = threadIdx.x;
    const int tx = tid & 15;
    const int ty = tid >> 4;
    const int m0 = blockIdx.y * 128;
    const int n0 = blockIdx.x * 64;

    float acc[8][4];
#pragma unroll
    for (int i = 0; i < 8; i++)
#pragma unroll
        for (int j = 0; j < 4; j++) acc[i][j] = 0.0f;

    for (int k0 = 0; k0 < DM; k0 += 16) {
#pragma unroll
        for (int i = 0; i < 2; i++) {
            int e = tid + i * 256;
            int r = e >> 2, c4 = e & 3;
            float4 f = *(const float4*)&g_ctx[(size_t)(m0 + r) * DM + k0 + c4 * 4];
            *(float4*)&As[r][c4 * 4] = f;
        }
        {
            int r = tid >> 4, c4 = tid & 15;
            float4 f = *(const float4*)&WO[(size_t)(k0 + r) * DM + n0 + c4 * 4];
            *(float4*)&Bs[r][c4 * 4] = f;
        }
        __syncthreads();
#pragma unroll
        for (int kk = 0; kk < 16; kk++) {
            float a[8];
#pragma unroll
            for (int i = 0; i < 8; i++) a[i] = As[ty * 8 + i][kk];
            float4 bv4 = *(const float4*)&Bs[kk][tx * 4];
#pragma unroll
            for (int i = 0; i < 8; i++) {
                acc[i][0] = fmaf(a[i], bv4.x, acc[i][0]);
                acc[i][1] = fmaf(a[i], bv4.y, acc[i][1]);
                acc[i][2] = fmaf(a[i], bv4.z, acc[i][2]);
                acc[i][3] = fmaf(a[i], bv4.w, acc[i][3]);
            }
        }
        __syncthreads();
    }

    float4 bb = *(const float4*)&bo[n0 + tx * 4];
#pragma unroll
    for (int i = 0; i < 8; i++) {
        int row = m0 + ty * 8 + i;
        float4 o;
        o.x = acc[i][0] + bb.x;
        o.y = acc[i][1] + bb.y;
        o.z = acc[i][2] + bb.z;
        o.w = acc[i][3] + bb.w;
        *(float4*)&out[(size_t)row * DM + n0 + tx * 4] = o;
    }
}

// ---------------------------------------------------------------------------
extern "C" void kernel_launch(void* const* d_in, const int* in_sizes, int n_in,
                              void* d_out, int out_size) {
    const float* v  = (const float*)d_in[0];
    const float* k  = (const float*)d_in[1];
    const float* q  = (const float*)d_in[2];
    const float* wq = (const float*)d_in[3];
    const float* bq = (const float*)d_in[4];
    const float* wk = (const float*)d_in[5];
    const float* bk = (const float*)d_in[6];
    const float* wv = (const float*)d_in[7];
    const float* bv = (const float*)d_in[8];
    const float* wo = (const float*)d_in[9];
    const float* bo = (const float*)d_in[10];

    float* out  = (float*)d_out;
    float* attn = out + (size_t)MROWS * DM;

    const int logits_smem = (128 * 68 + 64 * 132) * 4;           // 68608
    const int av_smem     = (128 * 68 + 64 * 68 + 256) * 4;      // 53248
    cudaFuncSetAttribute(logits_kernel,
                         cudaFuncAttributeMaxDynamicSharedMemorySize, logits_smem);
    cudaFuncSetAttribute(av_kernel,
                         cudaFuncAttributeMaxDynamicSharedMemorySize, av_smem);

    qkv_proj_kernel<<<dim3(DM / 64, MROWS / 128, 3), 256>>>(
        q, k, v, wq, wk, wv, bq, bk, bv);

    logits_kernel<<<dim3(Sc / 128, BH), 256, logits_smem>>>(attn);
    av_kernel<<<dim3(Sc / 128, BH), 256, av_smem>>>(attn);

    out_proj_kernel<<<dim3(DM / 64, MROWS / 128), 256>>>(wo, bo, out);
}

// round 5
// speedup vs baseline: 1.1092x; 1.1092x over previous
#include <cuda_runtime.h>
#include <cuda_bf16.h>

namespace {
constexpr int Bc = 2;
constexpr int Sc = 2048;
constexpr int DM = 1024;
constexpr int Hc = 16;
constexpr int DEPTH = 64;
constexpr int BH = Bc * Hc;
constexpr int MROWS = Bc * Sc;
constexpr float SCALE = 0.125f;
constexpr float NEG_BIG = -3.0e38f;
constexpr int BSTR = 40;   // bf16 row stride for smem tiles (conflict-free frags)
}

__device__ float g_qh[BH * Sc * DEPTH];
__device__ float g_kh[BH * Sc * DEPTH];
__device__ float g_vh[BH * Sc * DEPTH];
__device__ float g_ctx[MROWS * DM];
__device__ float g_m[BH * Sc];
__device__ float g_s[BH * Sc];

// ---------------- helpers ----------------
__device__ __forceinline__ void mma16816(float* d, const unsigned* a, const unsigned* b) {
    asm volatile(
        "mma.sync.aligned.m16n8k16.row.col.f32.bf16.bf16.f32 "
        "{%0,%1,%2,%3}, {%4,%5,%6,%7}, {%8,%9}, {%0,%1,%2,%3};"
        : "+f"(d[0]), "+f"(d[1]), "+f"(d[2]), "+f"(d[3])
        : "r"(a[0]), "r"(a[1]), "r"(a[2]), "r"(a[3]), "r"(b[0]), "r"(b[1]));
}
__device__ __forceinline__ void split_pack2(float a, float b, unsigned& hi, unsigned& lo) {
    __nv_bfloat16 ah = __float2bfloat16_rn(a);
    __nv_bfloat16 bh = __float2bfloat16_rn(b);
    __nv_bfloat16 al = __float2bfloat16_rn(a - __bfloat162float(ah));
    __nv_bfloat16 bl = __float2bfloat16_rn(b - __bfloat162float(bh));
    hi = (unsigned)__bfloat16_as_ushort(ah) | ((unsigned)__bfloat16_as_ushort(bh) << 16);
    lo = (unsigned)__bfloat16_as_ushort(al) | ((unsigned)__bfloat16_as_ushort(bl) << 16);
}
__device__ __forceinline__ float rmax16(float v) {
#pragma unroll
    for (int o = 8; o > 0; o >>= 1) v = fmaxf(v, __shfl_xor_sync(0xffffffffu, v, o));
    return v;
}
__device__ __forceinline__ float rsum16(float v) {
#pragma unroll
    for (int o = 8; o > 0; o >>= 1) v += __shfl_xor_sync(0xffffffffu, v, o);
    return v;
}

// ---------------------------------------------------------------------------
// HMMA projection GEMM: C = X @ W + bias. Tile 128(M)x128(N), K-chunks of 32.
// fp32 via bf16 hi/lo split (3 MMA terms). 8 warps: 4(M) x 2(N), warp 32x64.
// sel 0/1/2 -> head-split into g_qh/g_kh/g_vh; sel 3 -> g_ctx @ wo -> extout.
// ---------------------------------------------------------------------------
__global__ __launch_bounds__(256) void proj_mma(
    const float* __restrict__ q, const float* __restrict__ k, const float* __restrict__ v,
    const float* __restrict__ wq, const float* __restrict__ wk, const float* __restrict__ wv,
    const float* __restrict__ bq, const float* __restrict__ bk, const float* __restrict__ bv,
    const float* __restrict__ wo, const float* __restrict__ bo,
    float* __restrict__ extout, int selArg) {
    const int sel = (selArg < 0) ? (int)blockIdx.z : selArg;
    const float* X    = sel == 0 ? q  : sel == 1 ? k  : sel == 2 ? v  : g_ctx;
    const float* W    = sel == 0 ? wq : sel == 1 ? wk : sel == 2 ? wv : wo;
    const float* bias = sel == 0 ? bq : sel == 1 ? bk : sel == 2 ? bv : bo;
    float* dsth = sel == 0 ? g_qh : sel == 1 ? g_kh : g_vh;

    __shared__ __nv_bfloat16 Ah[128][BSTR], Al[128][BSTR];
    __shared__ __nv_bfloat16 Bh[128][BSTR], Bl[128][BSTR];

    const int tid = threadIdx.x;
    const int wid = tid >> 5, lane = tid & 31;
    const int g = lane >> 2, tig = lane & 3;
    const int wm = wid & 3, wn = wid >> 2;           // 4 x 2 warp grid
    const int m0 = blockIdx.y * 128, n0 = blockIdx.x * 128;

    float acc[2][8][4];
#pragma unroll
    for (int mi = 0; mi < 2; mi++)
#pragma unroll
        for (int nt = 0; nt < 8; nt++)
#pragma unroll
            for (int r = 0; r < 4; r++) acc[mi][nt][r] = 0.0f;

    const int nloc = tid & 127;                      // B-fill: column ownership
    const int khalf = (tid >> 7) * 16;
    const float* Wcol = W + n0 + nloc;

    for (int k0 = 0; k0 < DM; k0 += 32) {
        // A tile: 128 x 32 fp32 -> bf16 hi/lo, K-major rows
#pragma unroll
        for (int i = 0; i < 4; i++) {
            int e = tid + i * 256;
            int r = e >> 3, c4 = e & 7;
            float4 f = *(const float4*)&X[(size_t)(m0 + r) * DM + k0 + c4 * 4];
            unsigned h0, l0, h1, l1;
            split_pack2(f.x, f.y, h0, l0);
            split_pack2(f.z, f.w, h1, l1);
            *(unsigned*)&Ah[r][c4 * 4]     = h0;
            *(unsigned*)&Ah[r][c4 * 4 + 2] = h1;
            *(unsigned*)&Al[r][c4 * 4]     = l0;
            *(unsigned*)&Al[r][c4 * 4 + 2] = l1;
        }
        // B tile: Bs[n][k] = W[k][n0+n] (K-major per n row)
#pragma unroll
        for (int kp = 0; kp < 8; kp++) {
            int kk = k0 + khalf + kp * 2;
            float x0 = Wcol[(size_t)kk * DM];
            float x1 = Wcol[(size_t)(kk + 1) * DM];
            unsigned hi, lo;
            split_pack2(x0, x1, hi, lo);
            *(unsigned*)&Bh[nloc][khalf + kp * 2] = hi;
            *(unsigned*)&Bl[nloc][khalf + kp * 2] = lo;
        }
        __syncthreads();

#pragma unroll
        for (int ks = 0; ks < 32; ks += 16) {
            unsigned ah[2][4], al[2][4];
#pragma unroll
            for (int mi = 0; mi < 2; mi++) {
                int r0 = wm * 32 + mi * 16 + g;
                ah[mi][0] = *(const unsigned*)&Ah[r0][ks + tig * 2];
                ah[mi][1] = *(const unsigned*)&Ah[r0 + 8][ks + tig * 2];
                ah[mi][2] = *(const unsigned*)&Ah[r0][ks + tig * 2 + 8];
                ah[mi][3] = *(const unsigned*)&Ah[r0 + 8][ks + tig * 2 + 8];
                al[mi][0] = *(const unsigned*)&Al[r0][ks + tig * 2];
                al[mi][1] = *(const unsigned*)&Al[r0 + 8][ks + tig * 2];
                al[mi][2] = *(const unsigned*)&Al[r0][ks + tig * 2 + 8];
                al[mi][3] = *(const unsigned*)&Al[r0 + 8][ks + tig * 2 + 8];
            }
#pragma unroll
            for (int nt = 0; nt < 8; nt++) {
                int nc = wn * 64 + nt * 8 + g;
                unsigned bh[2], bl[2];
                bh[0] = *(const unsigned*)&Bh[nc][ks + tig * 2];
                bh[1] = *(const unsigned*)&Bh[nc][ks + tig * 2 + 8];
                bl[0] = *(const unsigned*)&Bl[nc][ks + tig * 2];
                bl[1] = *(const unsigned*)&Bl[nc][ks + tig * 2 + 8];
#pragma unroll
                for (int mi = 0; mi < 2; mi++) {
                    mma16816(acc[mi][nt], ah[mi], bh);
                    mma16816(acc[mi][nt], ah[mi], bl);
                    mma16816(acc[mi][nt], al[mi], bh);
                }
            }
        }
        __syncthreads();
    }

    // epilogue: fragment rows g/g+8, cols tig*2/+1 per n-tile
#pragma unroll
    for (int mi = 0; mi < 2; mi++) {
        int rbase = m0 + wm * 32 + mi * 16 + g;
#pragma unroll
        for (int nt = 0; nt < 8; nt++) {
            int col0 = n0 + wn * 64 + nt * 8 + tig * 2;
            float bx = bias[col0], by = bias[col0 + 1];
#pragma unroll
            for (int rr = 0; rr < 2; rr++) {
                int row = rbase + rr * 8;
                float v0 = acc[mi][nt][rr * 2]     + bx;
                float v1 = acc[mi][nt][rr * 2 + 1] + by;
                if (sel < 3) {
                    int hh = col0 >> 6, d = col0 & 63;
                    int b = row >> 11, s = row & 2047;
                    float2* p = (float2*)&dsth[(((size_t)(b * Hc + hh)) * Sc + s) * DEPTH + d];
                    *p = make_float2(v0, v1);
                } else {
                    *(float2*)&extout[(size_t)row * DM + col0] = make_float2(v0, v1);
                }
            }
        }
    }
}

// ---------------------------------------------------------------------------
// SIMT attention (proven passing version, unchanged)
// ---------------------------------------------------------------------------
__global__ __launch_bounds__(256, 2) void logits_kernel(float* __restrict__ attn) {
    extern __shared__ float sm[];
    float (*Qs)[68] = (float(*)[68])sm;
    float (*Kt)[132] = (float(*)[132])(sm + 128 * 68);
    const int bh = blockIdx.y, q0 = blockIdx.x * 128;
    const int tid = threadIdx.x, tx = tid & 15, ty = tid >> 4;
    const float* Qb = g_qh + (size_t)bh * Sc * DEPTH;
    const float* Kb = g_kh + (size_t)bh * Sc * DEPTH;
#pragma unroll
    for (int i = 0; i < 8; i++) {
        int e = tid + i * 256, r = e >> 4, c4 = e & 15;
        float4 f = *(const float4*)&Qb[(size_t)(q0 + r) * DEPTH + c4 * 4];
        *(float4*)&Qs[r][c4 * 4] = f;
    }
    float m_run[8], s_run[8];
#pragma unroll
    for (int i = 0; i < 8; i++) { m_run[i] = NEG_BIG; s_run[i] = 0.0f; }
    for (int k0 = 0; k0 < Sc; k0 += 128) {
        __syncthreads();
#pragma unroll
        for (int i = 0; i < 8; i++) {
            int e = tid + i * 256, r = e >> 4, c4 = e & 15;
            float4 f = *(const float4*)&Kb[(size_t)(k0 + r) * DEPTH + c4 * 4];
            Kt[c4 * 4 + 0][r] = f.x; Kt[c4 * 4 + 1][r] = f.y;
            Kt[c4 * 4 + 2][r] = f.z; Kt[c4 * 4 + 3][r] = f.w;
        }
        __syncthreads();
        float l[8][8];
#pragma unroll
        for (int i = 0; i < 8; i++)
#pragma unroll
            for (int j = 0; j < 8; j++) l[i][j] = 0.0f;
#pragma unroll 16
        for (int d = 0; d < 64; d++) {
            float a[8];
#pragma unroll
            for (int i = 0; i < 8; i++) a[i] = Qs[ty * 8 + i][d];
            float4 b0 = *(const float4*)&Kt[d][tx * 8];
            float4 b1 = *(const float4*)&Kt[d][tx * 8 + 4];
#pragma unroll
            for (int i = 0; i < 8; i++) {
                l[i][0] = fmaf(a[i], b0.x, l[i][0]); l[i][1] = fmaf(a[i], b0.y, l[i][1]);
                l[i][2] = fmaf(a[i], b0.z, l[i][2]); l[i][3] = fmaf(a[i], b0.w, l[i][3]);
                l[i][4] = fmaf(a[i], b1.x, l[i][4]); l[i][5] = fmaf(a[i], b1.y, l[i][5]);
                l[i][6] = fmaf(a[i], b1.z, l[i][6]); l[i][7] = fmaf(a[i], b1.w, l[i][7]);
            }
        }
#pragma unroll
        for (int i = 0; i < 8; i++) {
            int row = q0 + ty * 8 + i;
            float* arow = attn + ((size_t)bh * Sc + row) * Sc + k0 + tx * 8;
            float tmax = NEG_BIG;
#pragma unroll
            for (int j = 0; j < 8; j++) { l[i][j] *= SCALE; tmax = fmaxf(tmax, l[i][j]); }
            *(float4*)&arow[0] = make_float4(l[i][0], l[i][1], l[i][2], l[i][3]);
            *(float4*)&arow[4] = make_float4(l[i][4], l[i][5], l[i][6], l[i][7]);
            tmax = rmax16(tmax);
            float mnew = fmaxf(m_run[i], tmax), ps = 0.0f;
#pragma unroll
            for (int j = 0; j < 8; j++) ps += __expf(l[i][j] - mnew);
            ps = rsum16(ps);
            s_run[i] = s_run[i] * __expf(m_run[i] - mnew) + ps;
            m_run[i] = mnew;
        }
    }
    if (tx == 0) {
#pragma unroll
        for (int i = 0; i < 8; i++) {
            int row = q0 + ty * 8 + i;
            g_m[bh * Sc + row] = m_run[i];
            g_s[bh * Sc + row] = s_run[i];
        }
    }
}

__global__ __launch_bounds__(256) void av_kernel(float* __restrict__ attn) {
    extern __shared__ float sm[];
    float (*Ps)[68] = (float(*)[68])sm;
    float (*Vs)[68] = (float(*)[68])(sm + 128 * 68);
    float* msm = sm + 128 * 68 + 64 * 68;
    float* ssm = msm + 128;
    const int bh = blockIdx.y, q0 = blockIdx.x * 128;
    const int tid = threadIdx.x, tx = tid & 7, ty = tid >> 3;
    const float* Vb = g_vh + (size_t)bh * Sc * DEPTH;
    if (tid < 128) {
        msm[tid] = g_m[bh * Sc + q0 + tid];
        ssm[tid] = 1.0f / g_s[bh * Sc + q0 + tid];
    }
    float acc[4][8];
#pragma unroll
    for (int i = 0; i < 4; i++)
#pragma unroll
        for (int j = 0; j < 8; j++) acc[i][j] = 0.0f;
    for (int k0 = 0; k0 < Sc; k0 += 64) {
        __syncthreads();
#pragma unroll
        for (int i = 0; i < 4; i++) {
            int e = tid + i * 256, r = e >> 4, c4 = e & 15;
            float4 f = *(const float4*)&Vb[(size_t)(k0 + r) * DEPTH + c4 * 4];
            *(float4*)&Vs[r][c4 * 4] = f;
        }
#pragma unroll
        for (int i = 0; i < 8; i++) {
            int e = tid + i * 256, r = e >> 4, c4 = e & 15;
            float* gp = attn + ((size_t)bh * Sc + q0 + r) * Sc + k0 + c4 * 4;
            float4 x = *(const float4*)gp;
            float mm = msm[r], si = ssm[r];
            float4 p;
            p.x = __expf(x.x - mm) * si; p.y = __expf(x.y - mm) * si;
            p.z = __expf(x.z - mm) * si; p.w = __expf(x.w - mm) * si;
            *(float4*)gp = p;
            *(float4*)&Ps[r][c4 * 4] = p;
        }
        __syncthreads();
#pragma unroll 16
        for (int kk = 0; kk < 64; kk++) {
            float a[4];
#pragma unroll
            for (int i = 0; i < 4; i++) a[i] = Ps[ty * 4 + i][kk];
            float4 b0 = *(const float4*)&Vs[kk][tx * 8];
            float4 b1 = *(const float4*)&Vs[kk][tx * 8 + 4];
#pragma unroll
            for (int i = 0; i < 4; i++) {
                acc[i][0] = fmaf(a[i], b0.x, acc[i][0]); acc[i][1] = fmaf(a[i], b0.y, acc[i][1]);
                acc[i][2] = fmaf(a[i], b0.z, acc[i][2]); acc[i][3] = fmaf(a[i], b0.w, acc[i][3]);
                acc[i][4] = fmaf(a[i], b1.x, acc[i][4]); acc[i][5] = fmaf(a[i], b1.y, acc[i][5]);
                acc[i][6] = fmaf(a[i], b1.z, acc[i][6]); acc[i][7] = fmaf(a[i], b1.w, acc[i][7]);
            }
        }
    }
    const int b = bh >> 4, h = bh & 15;
#pragma unroll
    for (int i = 0; i < 4; i++) {
        int s = q0 + ty * 4 + i;
        float* cp = g_ctx + ((size_t)(b * Sc + s)) * DM + h * 64 + tx * 8;
        *(float4*)&cp[0] = make_float4(acc[i][0], acc[i][1], acc[i][2], acc[i][3]);
        *(float4*)&cp[4] = make_float4(acc[i][4], acc[i][5], acc[i][6], acc[i][7]);
    }
}

// ---------------------------------------------------------------------------
extern "C" void kernel_launch(void* const* d_in, const int* in_sizes, int n_in,
                              void* d_out, int out_size) {
    const float* v  = (const float*)d_in[0];
    const float* k  = (const float*)d_in[1];
    const float* q  = (const float*)d_in[2];
    const float* wq = (const float*)d_in[3];
    const float* bq = (const float*)d_in[4];
    const float* wk = (const float*)d_in[5];
    const float* bk = (const float*)d_in[6];
    const float* wv = (const float*)d_in[7];
    const float* bv = (const float*)d_in[8];
    const float* wo = (const float*)d_in[9];
    const float* bo = (const float*)d_in[10];

    float* out  = (float*)d_out;
    float* attn = out + (size_t)MROWS * DM;

    const int logits_smem = (128 * 68 + 64 * 132) * 4;
    const int av_smem     = (128 * 68 + 64 * 68 + 256) * 4;
    cudaFuncSetAttribute(logits_kernel, cudaFuncAttributeMaxDynamicSharedMemorySize, logits_smem);
    cudaFuncSetAttribute(av_kernel, cudaFuncAttributeMaxDynamicSharedMemorySize, av_smem);

    proj_mma<<<dim3(DM / 128, MROWS / 128, 3), 256>>>(
        q, k, v, wq, wk, wv, bq, bk, bv, wo, bo, out, -1);

    logits_kernel<<<dim3(Sc / 128, BH), 256, logits_smem>>>(attn);
    av_kernel<<<dim3(Sc / 128, BH), 256, av_smem>>>(attn);

    proj_mma<<<dim3(DM / 128, MROWS / 128, 1), 256>>>(
        q, k, v, wq, wk, wv, bq, bk, bv, wo, bo, out, 3);
}

// round 6
// speedup vs baseline: 1.1466x; 1.0338x over previous
#include <cuda_runtime.h>
#include <cuda_bf16.h>

namespace {
constexpr int Bc = 2;
constexpr int Sc = 2048;
constexpr int DM = 1024;
constexpr int Hc = 16;
constexpr int DEPTH = 64;
constexpr int BH = Bc * Hc;
constexpr int MROWS = Bc * Sc;
constexpr float SCALE = 0.125f;
constexpr float NEG_BIG = -3.0e38f;
constexpr int BSTR = 40;   // bf16 row stride for smem tiles (conflict-free frags)
}

__device__ float g_qh[BH * Sc * DEPTH];
__device__ float g_kh[BH * Sc * DEPTH];
__device__ float g_vh[BH * Sc * DEPTH];
__device__ float g_ctx[MROWS * DM];
__device__ float g_m[BH * Sc];
__device__ float g_s[BH * Sc];

// ---------------- helpers ----------------
__device__ __forceinline__ void mma16816(float* d, const unsigned* a, const unsigned* b) {
    asm volatile(
        "mma.sync.aligned.m16n8k16.row.col.f32.bf16.bf16.f32 "
        "{%0,%1,%2,%3}, {%4,%5,%6,%7}, {%8,%9}, {%0,%1,%2,%3};"
        : "+f"(d[0]), "+f"(d[1]), "+f"(d[2]), "+f"(d[3])
        : "r"(a[0]), "r"(a[1]), "r"(a[2]), "r"(a[3]), "r"(b[0]), "r"(b[1]));
}
__device__ __forceinline__ void split_pack2(float a, float b, unsigned& hi, unsigned& lo) {
    __nv_bfloat16 ah = __float2bfloat16_rn(a);
    __nv_bfloat16 bh = __float2bfloat16_rn(b);
    __nv_bfloat16 al = __float2bfloat16_rn(a - __bfloat162float(ah));
    __nv_bfloat16 bl = __float2bfloat16_rn(b - __bfloat162float(bh));
    hi = (unsigned)__bfloat16_as_ushort(ah) | ((unsigned)__bfloat16_as_ushort(bh) << 16);
    lo = (unsigned)__bfloat16_as_ushort(al) | ((unsigned)__bfloat16_as_ushort(bl) << 16);
}
__device__ __forceinline__ float rmax16(float v) {
#pragma unroll
    for (int o = 8; o > 0; o >>= 1) v = fmaxf(v, __shfl_xor_sync(0xffffffffu, v, o));
    return v;
}
__device__ __forceinline__ float rsum16(float v) {
#pragma unroll
    for (int o = 8; o > 0; o >>= 1) v += __shfl_xor_sync(0xffffffffu, v, o);
    return v;
}

// ---------------------------------------------------------------------------
// HMMA projection GEMM: C = X @ W + bias. Tile 128(M)x128(N), K-chunks of 32.
// fp32 via bf16 hi/lo split (3 MMA terms). 8 warps: 4(M) x 2(N), warp 32x64.
// sel 0/1/2 -> head-split into g_qh/g_kh/g_vh; sel 3 -> g_ctx @ wo -> extout.
// ---------------------------------------------------------------------------
__global__ __launch_bounds__(256) void proj_mma(
    const float* __restrict__ q, const float* __restrict__ k, const float* __restrict__ v,
    const float* __restrict__ wq, const float* __restrict__ wk, const float* __restrict__ wv,
    const float* __restrict__ bq, const float* __restrict__ bk, const float* __restrict__ bv,
    const float* __restrict__ wo, const float* __restrict__ bo,
    float* __restrict__ extout, int selArg) {
    const int sel = (selArg < 0) ? (int)blockIdx.z : selArg;
    const float* X    = sel == 0 ? q  : sel == 1 ? k  : sel == 2 ? v  : g_ctx;
    const float* W    = sel == 0 ? wq : sel == 1 ? wk : sel == 2 ? wv : wo;
    const float* bias = sel == 0 ? bq : sel == 1 ? bk : sel == 2 ? bv : bo;
    float* dsth = sel == 0 ? g_qh : sel == 1 ? g_kh : g_vh;

    __shared__ __nv_bfloat16 Ah[128][BSTR], Al[128][BSTR];
    __shared__ __nv_bfloat16 Bh[128][BSTR], Bl[128][BSTR];

    const int tid = threadIdx.x;
    const int wid = tid >> 5, lane = tid & 31;
    const int g = lane >> 2, tig = lane & 3;
    const int wm = wid & 3, wn = wid >> 2;           // 4 x 2 warp grid
    const int m0 = blockIdx.y * 128, n0 = blockIdx.x * 128;

    float acc[2][8][4];
#pragma unroll
    for (int mi = 0; mi < 2; mi++)
#pragma unroll
        for (int nt = 0; nt < 8; nt++)
#pragma unroll
            for (int r = 0; r < 4; r++) acc[mi][nt][r] = 0.0f;

    const int nloc = tid & 127;                      // B-fill: column ownership
    const int khalf = (tid >> 7) * 16;
    const float* Wcol = W + n0 + nloc;

    for (int k0 = 0; k0 < DM; k0 += 32) {
        // A tile: 128 x 32 fp32 -> bf16 hi/lo, K-major rows
#pragma unroll
        for (int i = 0; i < 4; i++) {
            int e = tid + i * 256;
            int r = e >> 3, c4 = e & 7;
            float4 f = *(const float4*)&X[(size_t)(m0 + r) * DM + k0 + c4 * 4];
            unsigned h0, l0, h1, l1;
            split_pack2(f.x, f.y, h0, l0);
            split_pack2(f.z, f.w, h1, l1);
            *(unsigned*)&Ah[r][c4 * 4]     = h0;
            *(unsigned*)&Ah[r][c4 * 4 + 2] = h1;
            *(unsigned*)&Al[r][c4 * 4]     = l0;
            *(unsigned*)&Al[r][c4 * 4 + 2] = l1;
        }
        // B tile: Bs[n][k] = W[k][n0+n] (K-major per n row)
#pragma unroll
        for (int kp = 0; kp < 8; kp++) {
            int kk = k0 + khalf + kp * 2;
            float x0 = Wcol[(size_t)kk * DM];
            float x1 = Wcol[(size_t)(kk + 1) * DM];
            unsigned hi, lo;
            split_pack2(x0, x1, hi, lo);
            *(unsigned*)&Bh[nloc][khalf + kp * 2] = hi;
            *(unsigned*)&Bl[nloc][khalf + kp * 2] = lo;
        }
        __syncthreads();

#pragma unroll
        for (int ks = 0; ks < 32; ks += 16) {
            unsigned ah[2][4], al[2][4];
#pragma unroll
            for (int mi = 0; mi < 2; mi++) {
                int r0 = wm * 32 + mi * 16 + g;
                ah[mi][0] = *(const unsigned*)&Ah[r0][ks + tig * 2];
                ah[mi][1] = *(const unsigned*)&Ah[r0 + 8][ks + tig * 2];
                ah[mi][2] = *(const unsigned*)&Ah[r0][ks + tig * 2 + 8];
                ah[mi][3] = *(const unsigned*)&Ah[r0 + 8][ks + tig * 2 + 8];
                al[mi][0] = *(const unsigned*)&Al[r0][ks + tig * 2];
                al[mi][1] = *(const unsigned*)&Al[r0 + 8][ks + tig * 2];
                al[mi][2] = *(const unsigned*)&Al[r0][ks + tig * 2 + 8];
                al[mi][3] = *(const unsigned*)&Al[r0 + 8][ks + tig * 2 + 8];
            }
#pragma unroll
            for (int nt = 0; nt < 8; nt++) {
                int nc = wn * 64 + nt * 8 + g;
                unsigned bh[2], bl[2];
                bh[0] = *(const unsigned*)&Bh[nc][ks + tig * 2];
                bh[1] = *(const unsigned*)&Bh[nc][ks + tig * 2 + 8];
                bl[0] = *(const unsigned*)&Bl[nc][ks + tig * 2];
                bl[1] = *(const unsigned*)&Bl[nc][ks + tig * 2 + 8];
#pragma unroll
                for (int mi = 0; mi < 2; mi++) {
                    mma16816(acc[mi][nt], ah[mi], bh);
                    mma16816(acc[mi][nt], ah[mi], bl);
                    mma16816(acc[mi][nt], al[mi], bh);
                }
            }
        }
        __syncthreads();
    }

    // epilogue: fragment rows g/g+8, cols tig*2/+1 per n-tile
#pragma unroll
    for (int mi = 0; mi < 2; mi++) {
        int rbase = m0 + wm * 32 + mi * 16 + g;
#pragma unroll
        for (int nt = 0; nt < 8; nt++) {
            int col0 = n0 + wn * 64 + nt * 8 + tig * 2;
            float bx = bias[col0], by = bias[col0 + 1];
#pragma unroll
            for (int rr = 0; rr < 2; rr++) {
                int row = rbase + rr * 8;
                float v0 = acc[mi][nt][rr * 2]     + bx;
                float v1 = acc[mi][nt][rr * 2 + 1] + by;
                if (sel < 3) {
                    int hh = col0 >> 6, d = col0 & 63;
                    int b = row >> 11, s = row & 2047;
                    float2* p = (float2*)&dsth[(((size_t)(b * Hc + hh)) * Sc + s) * DEPTH + d];
                    *p = make_float2(v0, v1);
                } else {
                    *(float2*)&extout[(size_t)row * DM + col0] = make_float2(v0, v1);
                }
            }
        }
    }
}

// ---------------------------------------------------------------------------
// SIMT attention (proven passing version, unchanged)
// ---------------------------------------------------------------------------
__global__ __launch_bounds__(256, 2) void logits_kernel(float* __restrict__ attn) {
    extern __shared__ float sm[];
    float (*Qs)[68] = (float(*)[68])sm;
    float (*Kt)[132] = (float(*)[132])(sm + 128 * 68);
    const int bh = blockIdx.y, q0 = blockIdx.x * 128;
    const int tid = threadIdx.x, tx = tid & 15, ty = tid >> 4;
    const float* Qb = g_qh + (size_t)bh * Sc * DEPTH;
    const float* Kb = g_kh + (size_t)bh * Sc * DEPTH;
#pragma unroll
    for (int i = 0; i < 8; i++) {
        int e = tid + i * 256, r = e >> 4, c4 = e & 15;
        float4 f = *(const float4*)&Qb[(size_t)(q0 + r) * DEPTH + c4 * 4];
        *(float4*)&Qs[r][c4 * 4] = f;
    }
    float m_run[8], s_run[8];
#pragma unroll
    for (int i = 0; i < 8; i++) { m_run[i] = NEG_BIG; s_run[i] = 0.0f; }
    for (int k0 = 0; k0 < Sc; k0 += 128) {
        __syncthreads();
#pragma unroll
        for (int i = 0; i < 8; i++) {
            int e = tid + i * 256, r = e >> 4, c4 = e & 15;
            float4 f = *(const float4*)&Kb[(size_t)(k0 + r) * DEPTH + c4 * 4];
            Kt[c4 * 4 + 0][r] = f.x; Kt[c4 * 4 + 1][r] = f.y;
            Kt[c4 * 4 + 2][r] = f.z; Kt[c4 * 4 + 3][r] = f.w;
        }
        __syncthreads();
        float l[8][8];
#pragma unroll
        for (int i = 0; i < 8; i++)
#pragma unroll
            for (int j = 0; j < 8; j++) l[i][j] = 0.0f;
#pragma unroll 16
        for (int d = 0; d < 64; d++) {
            float a[8];
#pragma unroll
            for (int i = 0; i < 8; i++) a[i] = Qs[ty * 8 + i][d];
            float4 b0 = *(const float4*)&Kt[d][tx * 8];
            float4 b1 = *(const float4*)&Kt[d][tx * 8 + 4];
#pragma unroll
            for (int i = 0; i < 8; i++) {
                l[i][0] = fmaf(a[i], b0.x, l[i][0]); l[i][1] = fmaf(a[i], b0.y, l[i][1]);
                l[i][2] = fmaf(a[i], b0.z, l[i][2]); l[i][3] = fmaf(a[i], b0.w, l[i][3]);
                l[i][4] = fmaf(a[i], b1.x, l[i][4]); l[i][5] = fmaf(a[i], b1.y, l[i][5]);
                l[i][6] = fmaf(a[i], b1.z, l[i][6]); l[i][7] = fmaf(a[i], b1.w, l[i][7]);
            }
        }
#pragma unroll
        for (int i = 0; i < 8; i++) {
            int row = q0 + ty * 8 + i;
            float* arow = attn + ((size_t)bh * Sc + row) * Sc + k0 + tx * 8;
            float tmax = NEG_BIG;
#pragma unroll
            for (int j = 0; j < 8; j++) { l[i][j] *= SCALE; tmax = fmaxf(tmax, l[i][j]); }
            *(float4*)&arow[0] = make_float4(l[i][0], l[i][1], l[i][2], l[i][3]);
            *(float4*)&arow[4] = make_float4(l[i][4], l[i][5], l[i][6], l[i][7]);
            tmax = rmax16(tmax);
            float mnew = fmaxf(m_run[i], tmax), ps = 0.0f;
#pragma unroll
            for (int j = 0; j < 8; j++) ps += __expf(l[i][j] - mnew);
            ps = rsum16(ps);
            s_run[i] = s_run[i] * __expf(m_run[i] - mnew) + ps;
            m_run[i] = mnew;
        }
    }
    if (tx == 0) {
#pragma unroll
        for (int i = 0; i < 8; i++) {
            int row = q0 + ty * 8 + i;
            g_m[bh * Sc + row] = m_run[i];
            g_s[bh * Sc + row] = s_run[i];
        }
    }
}

__global__ __launch_bounds__(256) void av_kernel(float* __restrict__ attn) {
    extern __shared__ float sm[];
    float (*Ps)[68] = (float(*)[68])sm;
    float (*Vs)[68] = (float(*)[68])(sm + 128 * 68);
    float* msm = sm + 128 * 68 + 64 * 68;
    float* ssm = msm + 128;
    const int bh = blockIdx.y, q0 = blockIdx.x * 128;
    const int tid = threadIdx.x, tx = tid & 7, ty = tid >> 3;
    const float* Vb = g_vh + (size_t)bh * Sc * DEPTH;
    if (tid < 128) {
        msm[tid] = g_m[bh * Sc + q0 + tid];
        ssm[tid] = 1.0f / g_s[bh * Sc + q0 + tid];
    }
    float acc[4][8];
#pragma unroll
    for (int i = 0; i < 4; i++)
#pragma unroll
        for (int j = 0; j < 8; j++) acc[i][j] = 0.0f;
    for (int k0 = 0; k0 < Sc; k0 += 64) {
        __syncthreads();
#pragma unroll
        for (int i = 0; i < 4; i++) {
            int e = tid + i * 256, r = e >> 4, c4 = e & 15;
            float4 f = *(const float4*)&Vb[(size_t)(k0 + r) * DEPTH + c4 * 4];
            *(float4*)&Vs[r][c4 * 4] = f;
        }
#pragma unroll
        for (int i = 0; i < 8; i++) {
            int e = tid + i * 256, r = e >> 4, c4 = e & 15;
            float* gp = attn + ((size_t)bh * Sc + q0 + r) * Sc + k0 + c4 * 4;
            float4 x = *(const float4*)gp;
            float mm = msm[r], si = ssm[r];
            float4 p;
            p.x = __expf(x.x - mm) * si; p.y = __expf(x.y - mm) * si;
            p.z = __expf(x.z - mm) * si; p.w = __expf(x.w - mm) * si;
            *(float4*)gp = p;
            *(float4*)&Ps[r][c4 * 4] = p;
        }
        __syncthreads();
#pragma unroll 16
        for (int kk = 0; kk < 64; kk++) {
            float a[4];
#pragma unroll
            for (int i = 0; i < 4; i++) a[i] = Ps[ty * 4 + i][kk];
            float4 b0 = *(const float4*)&Vs[kk][tx * 8];
            float4 b1 = *(const float4*)&Vs[kk][tx * 8 + 4];
#pragma unroll
            for (int i = 0; i < 4; i++) {
                acc[i][0] = fmaf(a[i], b0.x, acc[i][0]); acc[i][1] = fmaf(a[i], b0.y, acc[i][1]);
                acc[i][2] = fmaf(a[i], b0.z, acc[i][2]); acc[i][3] = fmaf(a[i], b0.w, acc[i][3]);
                acc[i][4] = fmaf(a[i], b1.x, acc[i][4]); acc[i][5] = fmaf(a[i], b1.y, acc[i][5]);
                acc[i][6] = fmaf(a[i], b1.z, acc[i][6]); acc[i][7] = fmaf(a[i], b1.w, acc[i][7]);
            }
        }
    }
    const int b = bh >> 4, h = bh & 15;
#pragma unroll
    for (int i = 0; i < 4; i++) {
        int s = q0 + ty * 4 + i;
        float* cp = g_ctx + ((size_t)(b * Sc + s)) * DM + h * 64 + tx * 8;
        *(float4*)&cp[0] = make_float4(acc[i][0], acc[i][1], acc[i][2], acc[i][3]);
        *(float4*)&cp[4] = make_float4(acc[i][4], acc[i][5], acc[i][6], acc[i][7]);
    }
}

// ---------------------------------------------------------------------------
extern "C" void kernel_launch(void* const* d_in, const int* in_sizes, int n_in,
                              void* d_out, int out_size) {
    const float* v  = (const float*)d_in[0];
    const float* k  = (const float*)d_in[1];
    const float* q  = (const float*)d_in[2];
    const float* wq = (const float*)d_in[3];
    const float* bq = (const float*)d_in[4];
    const float* wk = (const float*)d_in[5];
    const float* bk = (const float*)d_in[6];
    const float* wv = (const float*)d_in[7];
    const float* bv = (const float*)d_in[8];
    const float* wo = (const float*)d_in[9];
    const float* bo = (const float*)d_in[10];

    float* out  = (float*)d_out;
    float* attn = out + (size_t)MROWS * DM;

    const int logits_smem = (128 * 68 + 64 * 132) * 4;
    const int av_smem     = (128 * 68 + 64 * 68 + 256) * 4;
    cudaFuncSetAttribute(logits_kernel, cudaFuncAttributeMaxDynamicSharedMemorySize, logits_smem);
    cudaFuncSetAttribute(av_kernel, cudaFuncAttributeMaxDynamicSharedMemorySize, av_smem);

    proj_mma<<<dim3(DM / 128, MROWS / 128, 3), 256>>>(
        q, k, v, wq, wk, wv, bq, bk, bv, wo, bo, out, -1);

    logits_kernel<<<dim3(Sc / 128, BH), 256, logits_smem>>>(attn);
    av_kernel<<<dim3(Sc / 128, BH), 256, av_smem>>>(attn);

    proj_mma<<<dim3(DM / 128, MROWS / 128, 1), 256>>>(
        q, k, v, wq, wk, wv, bq, bk, bv, wo, bo, out, 3);
}

// round 7
// speedup vs baseline: 1.1507x; 1.0036x over previous
#include <cuda_runtime.h>
#include <cuda_bf16.h>

namespace {
constexpr int Bc = 2;
constexpr int Sc = 2048;
constexpr int DM = 1024;
constexpr int Hc = 16;
constexpr int DEPTH = 64;
constexpr int BH = Bc * Hc;
constexpr int MROWS = Bc * Sc;
constexpr float SCALE = 0.125f;
constexpr float NEG_BIG = -3.0e38f;
constexpr int BSTR = 40;   // bf16 row stride for smem tiles (conflict-free frags)
}

__device__ float g_qh[BH * Sc * DEPTH];
__device__ float g_kh[BH * Sc * DEPTH];
__device__ float g_vh[BH * Sc * DEPTH];
__device__ float g_ctx[MROWS * DM];
__device__ float g_m[BH * Sc];
__device__ float g_s[BH * Sc];

// ---------------- helpers ----------------
__device__ __forceinline__ void mma16816(float* d, const unsigned* a, const unsigned* b) {
    asm volatile(
        "mma.sync.aligned.m16n8k16.row.col.f32.bf16.bf16.f32 "
        "{%0,%1,%2,%3}, {%4,%5,%6,%7}, {%8,%9}, {%0,%1,%2,%3};"
        : "+f"(d[0]), "+f"(d[1]), "+f"(d[2]), "+f"(d[3])
        : "r"(a[0]), "r"(a[1]), "r"(a[2]), "r"(a[3]), "r"(b[0]), "r"(b[1]));
}
__device__ __forceinline__ void split_pack2(float a, float b, unsigned& hi, unsigned& lo) {
    __nv_bfloat16 ah = __float2bfloat16_rn(a);
    __nv_bfloat16 bh = __float2bfloat16_rn(b);
    __nv_bfloat16 al = __float2bfloat16_rn(a - __bfloat162float(ah));
    __nv_bfloat16 bl = __float2bfloat16_rn(b - __bfloat162float(bh));
    hi = (unsigned)__bfloat16_as_ushort(ah) | ((unsigned)__bfloat16_as_ushort(bh) << 16);
    lo = (unsigned)__bfloat16_as_ushort(al) | ((unsigned)__bfloat16_as_ushort(bl) << 16);
}
__device__ __forceinline__ float rmax16(float v) {
#pragma unroll
    for (int o = 8; o > 0; o >>= 1) v = fmaxf(v, __shfl_xor_sync(0xffffffffu, v, o));
    return v;
}
__device__ __forceinline__ float rsum16(float v) {
#pragma unroll
    for (int o = 8; o > 0; o >>= 1) v += __shfl_xor_sync(0xffffffffu, v, o);
    return v;
}

// ---------------------------------------------------------------------------
// HMMA projection GEMM: C = X @ W + bias. Tile 128(M)x128(N), K-chunks of 32.
// fp32 via bf16 hi/lo split (3 MMA terms). 8 warps: 4(M) x 2(N), warp 32x64.
// sel 0/1/2 -> head-split into g_qh/g_kh/g_vh; sel 3 -> g_ctx @ wo -> extout.
// ---------------------------------------------------------------------------
__global__ __launch_bounds__(256) void proj_mma(
    const float* __restrict__ q, const float* __restrict__ k, const float* __restrict__ v,
    const float* __restrict__ wq, const float* __restrict__ wk, const float* __restrict__ wv,
    const float* __restrict__ bq, const float* __restrict__ bk, const float* __restrict__ bv,
    const float* __restrict__ wo, const float* __restrict__ bo,
    float* __restrict__ extout, int selArg) {
    const int sel = (selArg < 0) ? (int)blockIdx.z : selArg;
    const float* X    = sel == 0 ? q  : sel == 1 ? k  : sel == 2 ? v  : g_ctx;
    const float* W    = sel == 0 ? wq : sel == 1 ? wk : sel == 2 ? wv : wo;
    const float* bias = sel == 0 ? bq : sel == 1 ? bk : sel == 2 ? bv : bo;
    float* dsth = sel == 0 ? g_qh : sel == 1 ? g_kh : g_vh;

    __shared__ __nv_bfloat16 Ah[128][BSTR], Al[128][BSTR];
    __shared__ __nv_bfloat16 Bh[128][BSTR], Bl[128][BSTR];

    const int tid = threadIdx.x;
    const int wid = tid >> 5, lane = tid & 31;
    const int g = lane >> 2, tig = lane & 3;
    const int wm = wid & 3, wn = wid >> 2;           // 4 x 2 warp grid
    const int m0 = blockIdx.y * 128, n0 = blockIdx.x * 128;

    float acc[2][8][4];
#pragma unroll
    for (int mi = 0; mi < 2; mi++)
#pragma unroll
        for (int nt = 0; nt < 8; nt++)
#pragma unroll
            for (int r = 0; r < 4; r++) acc[mi][nt][r] = 0.0f;

    const int nloc = tid & 127;                      // B-fill: column ownership
    const int khalf = (tid >> 7) * 16;
    const float* Wcol = W + n0 + nloc;

    for (int k0 = 0; k0 < DM; k0 += 32) {
        // A tile: 128 x 32 fp32 -> bf16 hi/lo, K-major rows
#pragma unroll
        for (int i = 0; i < 4; i++) {
            int e = tid + i * 256;
            int r = e >> 3, c4 = e & 7;
            float4 f = *(const float4*)&X[(size_t)(m0 + r) * DM + k0 + c4 * 4];
            unsigned h0, l0, h1, l1;
            split_pack2(f.x, f.y, h0, l0);
            split_pack2(f.z, f.w, h1, l1);
            *(unsigned*)&Ah[r][c4 * 4]     = h0;
            *(unsigned*)&Ah[r][c4 * 4 + 2] = h1;
            *(unsigned*)&Al[r][c4 * 4]     = l0;
            *(unsigned*)&Al[r][c4 * 4 + 2] = l1;
        }
        // B tile: Bs[n][k] = W[k][n0+n] (K-major per n row)
#pragma unroll
        for (int kp = 0; kp < 8; kp++) {
            int kk = k0 + khalf + kp * 2;
            float x0 = Wcol[(size_t)kk * DM];
            float x1 = Wcol[(size_t)(kk + 1) * DM];
            unsigned hi, lo;
            split_pack2(x0, x1, hi, lo);
            *(unsigned*)&Bh[nloc][khalf + kp * 2] = hi;
            *(unsigned*)&Bl[nloc][khalf + kp * 2] = lo;
        }
        __syncthreads();

#pragma unroll
        for (int ks = 0; ks < 32; ks += 16) {
            unsigned ah[2][4], al[2][4];
#pragma unroll
            for (int mi = 0; mi < 2; mi++) {
                int r0 = wm * 32 + mi * 16 + g;
                ah[mi][0] = *(const unsigned*)&Ah[r0][ks + tig * 2];
                ah[mi][1] = *(const unsigned*)&Ah[r0 + 8][ks + tig * 2];
                ah[mi][2] = *(const unsigned*)&Ah[r0][ks + tig * 2 + 8];
                ah[mi][3] = *(const unsigned*)&Ah[r0 + 8][ks + tig * 2 + 8];
                al[mi][0] = *(const unsigned*)&Al[r0][ks + tig * 2];
                al[mi][1] = *(const unsigned*)&Al[r0 + 8][ks + tig * 2];
                al[mi][2] = *(const unsigned*)&Al[r0][ks + tig * 2 + 8];
                al[mi][3] = *(const unsigned*)&Al[r0 + 8][ks + tig * 2 + 8];
            }
#pragma unroll
            for (int nt = 0; nt < 8; nt++) {
                int nc = wn * 64 + nt * 8 + g;
                unsigned bh[2], bl[2];
                bh[0] = *(const unsigned*)&Bh[nc][ks + tig * 2];
                bh[1] = *(const unsigned*)&Bh[nc][ks + tig * 2 + 8];
                bl[0] = *(const unsigned*)&Bl[nc][ks + tig * 2];
                bl[1] = *(const unsigned*)&Bl[nc][ks + tig * 2 + 8];
#pragma unroll
                for (int mi = 0; mi < 2; mi++) {
                    mma16816(acc[mi][nt], ah[mi], bh);
                    mma16816(acc[mi][nt], ah[mi], bl);
                    mma16816(acc[mi][nt], al[mi], bh);
                }
            }
        }
        __syncthreads();
    }

    // epilogue: fragment rows g/g+8, cols tig*2/+1 per n-tile
#pragma unroll
    for (int mi = 0; mi < 2; mi++) {
        int rbase = m0 + wm * 32 + mi * 16 + g;
#pragma unroll
        for (int nt = 0; nt < 8; nt++) {
            int col0 = n0 + wn * 64 + nt * 8 + tig * 2;
            float bx = bias[col0], by = bias[col0 + 1];
#pragma unroll
            for (int rr = 0; rr < 2; rr++) {
                int row = rbase + rr * 8;
                float v0 = acc[mi][nt][rr * 2]     + bx;
                float v1 = acc[mi][nt][rr * 2 + 1] + by;
                if (sel < 3) {
                    int hh = col0 >> 6, d = col0 & 63;
                    int b = row >> 11, s = row & 2047;
                    float2* p = (float2*)&dsth[(((size_t)(b * Hc + hh)) * Sc + s) * DEPTH + d];
                    *p = make_float2(v0, v1);
                } else {
                    *(float2*)&extout[(size_t)row * DM + col0] = make_float2(v0, v1);
                }
            }
        }
    }
}

// ---------------------------------------------------------------------------
// SIMT attention (proven passing version, unchanged)
// ---------------------------------------------------------------------------
__global__ __launch_bounds__(256, 2) void logits_kernel(float* __restrict__ attn) {
    extern __shared__ float sm[];
    float (*Qs)[68] = (float(*)[68])sm;
    float (*Kt)[132] = (float(*)[132])(sm + 128 * 68);
    const int bh = blockIdx.y, q0 = blockIdx.x * 128;
    const int tid = threadIdx.x, tx = tid & 15, ty = tid >> 4;
    const float* Qb = g_qh + (size_t)bh * Sc * DEPTH;
    const float* Kb = g_kh + (size_t)bh * Sc * DEPTH;
#pragma unroll
    for (int i = 0; i < 8; i++) {
        int e = tid + i * 256, r = e >> 4, c4 = e & 15;
        float4 f = *(const float4*)&Qb[(size_t)(q0 + r) * DEPTH + c4 * 4];
        *(float4*)&Qs[r][c4 * 4] = f;
    }
    float m_run[8], s_run[8];
#pragma unroll
    for (int i = 0; i < 8; i++) { m_run[i] = NEG_BIG; s_run[i] = 0.0f; }
    for (int k0 = 0; k0 < Sc; k0 += 128) {
        __syncthreads();
#pragma unroll
        for (int i = 0; i < 8; i++) {
            int e = tid + i * 256, r = e >> 4, c4 = e & 15;
            float4 f = *(const float4*)&Kb[(size_t)(k0 + r) * DEPTH + c4 * 4];
            Kt[c4 * 4 + 0][r] = f.x; Kt[c4 * 4 + 1][r] = f.y;
            Kt[c4 * 4 + 2][r] = f.z; Kt[c4 * 4 + 3][r] = f.w;
        }
        __syncthreads();
        float l[8][8];
#pragma unroll
        for (int i = 0; i < 8; i++)
#pragma unroll
            for (int j = 0; j < 8; j++) l[i][j] = 0.0f;
#pragma unroll 16
        for (int d = 0; d < 64; d++) {
            float a[8];
#pragma unroll
            for (int i = 0; i < 8; i++) a[i] = Qs[ty * 8 + i][d];
            float4 b0 = *(const float4*)&Kt[d][tx * 8];
            float4 b1 = *(const float4*)&Kt[d][tx * 8 + 4];
#pragma unroll
            for (int i = 0; i < 8; i++) {
                l[i][0] = fmaf(a[i], b0.x, l[i][0]); l[i][1] = fmaf(a[i], b0.y, l[i][1]);
                l[i][2] = fmaf(a[i], b0.z, l[i][2]); l[i][3] = fmaf(a[i], b0.w, l[i][3]);
                l[i][4] = fmaf(a[i], b1.x, l[i][4]); l[i][5] = fmaf(a[i], b1.y, l[i][5]);
                l[i][6] = fmaf(a[i], b1.z, l[i][6]); l[i][7] = fmaf(a[i], b1.w, l[i][7]);
            }
        }
#pragma unroll
        for (int i = 0; i < 8; i++) {
            int row = q0 + ty * 8 + i;
            float* arow = attn + ((size_t)bh * Sc + row) * Sc + k0 + tx * 8;
            float tmax = NEG_BIG;
#pragma unroll
            for (int j = 0; j < 8; j++) { l[i][j] *= SCALE; tmax = fmaxf(tmax, l[i][j]); }
            *(float4*)&arow[0] = make_float4(l[i][0], l[i][1], l[i][2], l[i][3]);
            *(float4*)&arow[4] = make_float4(l[i][4], l[i][5], l[i][6], l[i][7]);
            tmax = rmax16(tmax);
            float mnew = fmaxf(m_run[i], tmax), ps = 0.0f;
#pragma unroll
            for (int j = 0; j < 8; j++) ps += __expf(l[i][j] - mnew);
            ps = rsum16(ps);
            s_run[i] = s_run[i] * __expf(m_run[i] - mnew) + ps;
            m_run[i] = mnew;
        }
    }
    if (tx == 0) {
#pragma unroll
        for (int i = 0; i < 8; i++) {
            int row = q0 + ty * 8 + i;
            g_m[bh * Sc + row] = m_run[i];
            g_s[bh * Sc + row] = s_run[i];
        }
    }
}

__global__ __launch_bounds__(256) void av_kernel(float* __restrict__ attn) {
    extern __shared__ float sm[];
    float (*Ps)[68] = (float(*)[68])sm;
    float (*Vs)[68] = (float(*)[68])(sm + 128 * 68);
    float* msm = sm + 128 * 68 + 64 * 68;
    float* ssm = msm + 128;
    const int bh = blockIdx.y, q0 = blockIdx.x * 128;
    const int tid = threadIdx.x, tx = tid & 7, ty = tid >> 3;
    const float* Vb = g_vh + (size_t)bh * Sc * DEPTH;
    if (tid < 128) {
        msm[tid] = g_m[bh * Sc + q0 + tid];
        ssm[tid] = 1.0f / g_s[bh * Sc + q0 + tid];
    }
    float acc[4][8];
#pragma unroll
    for (int i = 0; i < 4; i++)
#pragma unroll
        for (int j = 0; j < 8; j++) acc[i][j] = 0.0f;
    for (int k0 = 0; k0 < Sc; k0 += 64) {
        __syncthreads();
#pragma unroll
        for (int i = 0; i < 4; i++) {
            int e = tid + i * 256, r = e >> 4, c4 = e & 15;
            float4 f = *(const float4*)&Vb[(size_t)(k0 + r) * DEPTH + c4 * 4];
            *(float4*)&Vs[r][c4 * 4] = f;
        }
#pragma unroll
        for (int i = 0; i < 8; i++) {
            int e = tid + i * 256, r = e >> 4, c4 = e & 15;
            float* gp = attn + ((size_t)bh * Sc + q0 + r) * Sc + k0 + c4 * 4;
            float4 x = *(const float4*)gp;
            float mm = msm[r], si = ssm[r];
            float4 p;
            p.x = __expf(x.x - mm) * si; p.y = __expf(x.y - mm) * si;
            p.z = __expf(x.z - mm) * si; p.w = __expf(x.w - mm) * si;
            *(float4*)gp = p;
            *(float4*)&Ps[r][c4 * 4] = p;
        }
        __syncthreads();
#pragma unroll 16
        for (int kk = 0; kk < 64; kk++) {
            float a[4];
#pragma unroll
            for (int i = 0; i < 4; i++) a[i] = Ps[ty * 4 + i][kk];
            float4 b0 = *(const float4*)&Vs[kk][tx * 8];
            float4 b1 = *(const float4*)&Vs[kk][tx * 8 + 4];
#pragma unroll
            for (int i = 0; i < 4; i++) {
                acc[i][0] = fmaf(a[i], b0.x, acc[i][0]); acc[i][1] = fmaf(a[i], b0.y, acc[i][1]);
                acc[i][2] = fmaf(a[i], b0.z, acc[i][2]); acc[i][3] = fmaf(a[i], b0.w, acc[i][3]);
                acc[i][4] = fmaf(a[i], b1.x, acc[i][4]); acc[i][5] = fmaf(a[i], b1.y, acc[i][5]);
                acc[i][6] = fmaf(a[i], b1.z, acc[i][6]); acc[i][7] = fmaf(a[i], b1.w, acc[i][7]);
            }
        }
    }
    const int b = bh >> 4, h = bh & 15;
#pragma unroll
    for (int i = 0; i < 4; i++) {
        int s = q0 + ty * 4 + i;
        float* cp = g_ctx + ((size_t)(b * Sc + s)) * DM + h * 64 + tx * 8;
        *(float4*)&cp[0] = make_float4(acc[i][0], acc[i][1], acc[i][2], acc[i][3]);
        *(float4*)&cp[4] = make_float4(acc[i][4], acc[i][5], acc[i][6], acc[i][7]);
    }
}

// ---------------------------------------------------------------------------
extern "C" void kernel_launch(void* const* d_in, const int* in_sizes, int n_in,
                              void* d_out, int out_size) {
    const float* v  = (const float*)d_in[0];
    const float* k  = (const float*)d_in[1];
    const float* q  = (const float*)d_in[2];
    const float* wq = (const float*)d_in[3];
    const float* bq = (const float*)d_in[4];
    const float* wk = (const float*)d_in[5];
    const float* bk = (const float*)d_in[6];
    const float* wv = (const float*)d_in[7];
    const float* bv = (const float*)d_in[8];
    const float* wo = (const float*)d_in[9];
    const float* bo = (const float*)d_in[10];

    float* out  = (float*)d_out;
    float* attn = out + (size_t)MROWS * DM;

    const int logits_smem = (128 * 68 + 64 * 132) * 4;
    const int av_smem     = (128 * 68 + 64 * 68 + 256) * 4;
    cudaFuncSetAttribute(logits_kernel, cudaFuncAttributeMaxDynamicSharedMemorySize, logits_smem);
    cudaFuncSetAttribute(av_kernel, cudaFuncAttributeMaxDynamicSharedMemorySize, av_smem);

    proj_mma<<<dim3(DM / 128, MROWS / 128, 3), 256>>>(
        q, k, v, wq, wk, wv, bq, bk, bv, wo, bo, out, -1);

    logits_kernel<<<dim3(Sc / 128, BH), 256, logits_smem>>>(attn);
    av_kernel<<<dim3(Sc / 128, BH), 256, av_smem>>>(attn);

    proj_mma<<<dim3(DM / 128, MROWS / 128, 1), 256>>>(
        q, k, v, wq, wk, wv, bq, bk, bv, wo, bo, out, 3);
}

// round 9
// speedup vs baseline: 1.6509x; 1.4348x over previous
#include <cuda_runtime.h>
#include <cuda_bf16.h>

namespace {
constexpr int Bc = 2;
constexpr int Sc = 2048;
constexpr int DM = 1024;
constexpr int Hc = 16;
constexpr int DEPTH = 64;
constexpr int BH = Bc * Hc;
constexpr int MROWS = Bc * Sc;
constexpr float SCALE = 0.125f;
constexpr float NEG_BIG = -3.0e38f;
constexpr int BSTR = 40;     // proj smem stride
constexpr int QSTR = 72;     // attention smem stride (bf16)
}

__device__ float g_qh[BH * Sc * DEPTH];
__device__ float g_kh[BH * Sc * DEPTH];
__device__ float g_vh[BH * Sc * DEPTH];
__device__ float g_ctx[MROWS * DM];

// ---------------- helpers ----------------
__device__ __forceinline__ void mma16816(float* d, const unsigned* a, const unsigned* b) {
    asm volatile(
        "mma.sync.aligned.m16n8k16.row.col.f32.bf16.bf16.f32 "
        "{%0,%1,%2,%3}, {%4,%5,%6,%7}, {%8,%9}, {%0,%1,%2,%3};"
        : "+f"(d[0]), "+f"(d[1]), "+f"(d[2]), "+f"(d[3])
        : "r"(a[0]), "r"(a[1]), "r"(a[2]), "r"(a[3]), "r"(b[0]), "r"(b[1]));
}
__device__ __forceinline__ void split_pack2(float a, float b, unsigned& hi, unsigned& lo) {
    __nv_bfloat16 ah = __float2bfloat16_rn(a);
    __nv_bfloat16 bh = __float2bfloat16_rn(b);
    __nv_bfloat16 al = __float2bfloat16_rn(a - __bfloat162float(ah));
    __nv_bfloat16 bl = __float2bfloat16_rn(b - __bfloat162float(bh));
    hi = (unsigned)__bfloat16_as_ushort(ah) | ((unsigned)__bfloat16_as_ushort(bh) << 16);
    lo = (unsigned)__bfloat16_as_ushort(al) | ((unsigned)__bfloat16_as_ushort(bl) << 16);
}

// ---------------------------------------------------------------------------
// HMMA projection GEMM (proven in R7, unchanged).
// ---------------------------------------------------------------------------
__global__ __launch_bounds__(256) void proj_mma(
    const float* __restrict__ q, const float* __restrict__ k, const float* __restrict__ v,
    const float* __restrict__ wq, const float* __restrict__ wk, const float* __restrict__ wv,
    const float* __restrict__ bq, const float* __restrict__ bk, const float* __restrict__ bv,
    const float* __restrict__ wo, const float* __restrict__ bo,
    float* __restrict__ extout, int selArg) {
    const int sel = (selArg < 0) ? (int)blockIdx.z : selArg;
    const float* X    = sel == 0 ? q  : sel == 1 ? k  : sel == 2 ? v  : g_ctx;
    const float* W    = sel == 0 ? wq : sel == 1 ? wk : sel == 2 ? wv : wo;
    const float* bias = sel == 0 ? bq : sel == 1 ? bk : sel == 2 ? bv : bo;
    float* dsth = sel == 0 ? g_qh : sel == 1 ? g_kh : g_vh;

    __shared__ __nv_bfloat16 Ah[128][BSTR], Al[128][BSTR];
    __shared__ __nv_bfloat16 Bh[128][BSTR], Bl[128][BSTR];

    const int tid = threadIdx.x;
    const int wid = tid >> 5, lane = tid & 31;
    const int g = lane >> 2, tig = lane & 3;
    const int wm = wid & 3, wn = wid >> 2;
    const int m0 = blockIdx.y * 128, n0 = blockIdx.x * 128;

    float acc[2][8][4];
#pragma unroll
    for (int mi = 0; mi < 2; mi++)
#pragma unroll
        for (int nt = 0; nt < 8; nt++)
#pragma unroll
            for (int r = 0; r < 4; r++) acc[mi][nt][r] = 0.0f;

    const int nloc = tid & 127;
    const int khalf = (tid >> 7) * 16;
    const float* Wcol = W + n0 + nloc;

    for (int k0 = 0; k0 < DM; k0 += 32) {
#pragma unroll
        for (int i = 0; i < 4; i++) {
            int e = tid + i * 256;
            int r = e >> 3, c4 = e & 7;
            float4 f = *(const float4*)&X[(size_t)(m0 + r) * DM + k0 + c4 * 4];
            unsigned h0, l0, h1, l1;
            split_pack2(f.x, f.y, h0, l0);
            split_pack2(f.z, f.w, h1, l1);
            *(unsigned*)&Ah[r][c4 * 4]     = h0;
            *(unsigned*)&Ah[r][c4 * 4 + 2] = h1;
            *(unsigned*)&Al[r][c4 * 4]     = l0;
            *(unsigned*)&Al[r][c4 * 4 + 2] = l1;
        }
#pragma unroll
        for (int kp = 0; kp < 8; kp++) {
            int kk = k0 + khalf + kp * 2;
            float x0 = Wcol[(size_t)kk * DM];
            float x1 = Wcol[(size_t)(kk + 1) * DM];
            unsigned hi, lo;
            split_pack2(x0, x1, hi, lo);
            *(unsigned*)&Bh[nloc][khalf + kp * 2] = hi;
            *(unsigned*)&Bl[nloc][khalf + kp * 2] = lo;
        }
        __syncthreads();

#pragma unroll
        for (int ks = 0; ks < 32; ks += 16) {
            unsigned ah[2][4], al[2][4];
#pragma unroll
            for (int mi = 0; mi < 2; mi++) {
                int r0 = wm * 32 + mi * 16 + g;
                ah[mi][0] = *(const unsigned*)&Ah[r0][ks + tig * 2];
                ah[mi][1] = *(const unsigned*)&Ah[r0 + 8][ks + tig * 2];
                ah[mi][2] = *(const unsigned*)&Ah[r0][ks + tig * 2 + 8];
                ah[mi][3] = *(const unsigned*)&Ah[r0 + 8][ks + tig * 2 + 8];
                al[mi][0] = *(const unsigned*)&Al[r0][ks + tig * 2];
                al[mi][1] = *(const unsigned*)&Al[r0 + 8][ks + tig * 2];
                al[mi][2] = *(const unsigned*)&Al[r0][ks + tig * 2 + 8];
                al[mi][3] = *(const unsigned*)&Al[r0 + 8][ks + tig * 2 + 8];
            }
#pragma unroll
            for (int nt = 0; nt < 8; nt++) {
                int nc = wn * 64 + nt * 8 + g;
                unsigned bh2[2], bl2[2];
                bh2[0] = *(const unsigned*)&Bh[nc][ks + tig * 2];
                bh2[1] = *(const unsigned*)&Bh[nc][ks + tig * 2 + 8];
                bl2[0] = *(const unsigned*)&Bl[nc][ks + tig * 2];
                bl2[1] = *(const unsigned*)&Bl[nc][ks + tig * 2 + 8];
#pragma unroll
                for (int mi = 0; mi < 2; mi++) {
                    mma16816(acc[mi][nt], ah[mi], bh2);
                    mma16816(acc[mi][nt], ah[mi], bl2);
                    mma16816(acc[mi][nt], al[mi], bh2);
                }
            }
        }
        __syncthreads();
    }

#pragma unroll
    for (int mi = 0; mi < 2; mi++) {
        int rbase = m0 + wm * 32 + mi * 16 + g;
#pragma unroll
        for (int nt = 0; nt < 8; nt++) {
            int col0 = n0 + wn * 64 + nt * 8 + tig * 2;
            float bx = bias[col0], by = bias[col0 + 1];
#pragma unroll
            for (int rr = 0; rr < 2; rr++) {
                int row = rbase + rr * 8;
                float v0 = acc[mi][nt][rr * 2]     + bx;
                float v1 = acc[mi][nt][rr * 2 + 1] + by;
                if (sel < 3) {
                    int hh = col0 >> 6, d = col0 & 63;
                    int b = row >> 11, s = row & 2047;
                    *(float2*)&dsth[(((size_t)(b * Hc + hh)) * Sc + s) * DEPTH + d] =
                        make_float2(v0, v1);
                } else {
                    *(float2*)&extout[(size_t)row * DM + col0] = make_float2(v0, v1);
                }
            }
        }
    }
}

// ---------------------------------------------------------------------------
// Fused HMMA attention. One CTA per (bh, 128 q-rows), 8 warps = 4(M) x 2(Kn).
// ---------------------------------------------------------------------------
__global__ __launch_bounds__(256) void fused_attn(float* __restrict__ attn) {
    extern __shared__ char smraw[];
    __nv_bfloat16* Qh = (__nv_bfloat16*)smraw;      // [128][QSTR]
    __nv_bfloat16* Ql = Qh + 128 * QSTR;
    __nv_bfloat16* Kh = Ql + 128 * QSTR;            // [64][QSTR]
    __nv_bfloat16* Kl = Kh + 64 * QSTR;
    __nv_bfloat16* Vh = Kl + 64 * QSTR;             // transposed [d][key]
    __nv_bfloat16* Vl = Vh + 64 * QSTR;
    float* mfin = (float*)(Vl + 64 * QSTR);         // [128]
    float* sinv = mfin + 128;                       // [128]
    float* pbuf = sinv + 128;                       // [2][128][2]
    float* obuf = (float*)Kh;                       // alias (used after last sync)

    const int bh = blockIdx.y, q0 = blockIdx.x * 128;
    const int tid = threadIdx.x;
    const int wid = tid >> 5, lane = tid & 31;
    const int g = lane >> 2, tig = lane & 3;
    const int wm = wid & 3, wn = wid >> 2;

    const float* Qb = g_qh + (size_t)bh * Sc * DEPTH;
    const float* Kb = g_kh + (size_t)bh * Sc * DEPTH;
    const float* Vb = g_vh + (size_t)bh * Sc * DEPTH;

    // Q tile (scaled; exact power of two)
#pragma unroll
    for (int i = 0; i < 8; i++) {
        int e = tid + i * 256, r = e >> 4, c4 = e & 15;
        float4 f = *(const float4*)&Qb[(size_t)(q0 + r) * DEPTH + c4 * 4];
        f.x *= SCALE; f.y *= SCALE; f.z *= SCALE; f.w *= SCALE;
        unsigned h0, l0, h1, l1;
        split_pack2(f.x, f.y, h0, l0);
        split_pack2(f.z, f.w, h1, l1);
        *(unsigned*)&Qh[r * QSTR + c4 * 4]     = h0;
        *(unsigned*)&Qh[r * QSTR + c4 * 4 + 2] = h1;
        *(unsigned*)&Ql[r * QSTR + c4 * 4]     = l0;
        *(unsigned*)&Ql[r * QSTR + c4 * 4 + 2] = l1;
    }

    float m_run[4], s_run[4];
#pragma unroll
    for (int i = 0; i < 4; i++) { m_run[i] = NEG_BIG; s_run[i] = 0.0f; }

    // ================= PASS A =================
    for (int t = 0; t < 32; t++) {
        const int k0 = t * 64;
        __syncthreads();
#pragma unroll
        for (int i = 0; i < 4; i++) {
            int e = tid + i * 256, r = e >> 4, c4 = e & 15;
            float4 f = *(const float4*)&Kb[(size_t)(k0 + r) * DEPTH + c4 * 4];
            unsigned h0, l0, h1, l1;
            split_pack2(f.x, f.y, h0, l0);
            split_pack2(f.z, f.w, h1, l1);
            *(unsigned*)&Kh[r * QSTR + c4 * 4]     = h0;
            *(unsigned*)&Kh[r * QSTR + c4 * 4 + 2] = h1;
            *(unsigned*)&Kl[r * QSTR + c4 * 4]     = l0;
            *(unsigned*)&Kl[r * QSTR + c4 * 4 + 2] = l1;
        }
        __syncthreads();

        float lc[2][4][4];
#pragma unroll
        for (int mi = 0; mi < 2; mi++)
#pragma unroll
            for (int nt = 0; nt < 4; nt++)
#pragma unroll
                for (int r = 0; r < 4; r++) lc[mi][nt][r] = 0.0f;
#pragma unroll
        for (int ks = 0; ks < 4; ks++) {
            unsigned aqh[2][4], aql[2][4];
#pragma unroll
            for (int mi = 0; mi < 2; mi++) {
                int base = (wm * 32 + mi * 16 + g) * QSTR + ks * 16 + tig * 2;
                aqh[mi][0] = *(const unsigned*)&Qh[base];
                aqh[mi][1] = *(const unsigned*)&Qh[base + 8 * QSTR];
                aqh[mi][2] = *(const unsigned*)&Qh[base + 8];
                aqh[mi][3] = *(const unsigned*)&Qh[base + 8 * QSTR + 8];
                aql[mi][0] = *(const unsigned*)&Ql[base];
                aql[mi][1] = *(const unsigned*)&Ql[base + 8 * QSTR];
                aql[mi][2] = *(const unsigned*)&Ql[base + 8];
                aql[mi][3] = *(const unsigned*)&Ql[base + 8 * QSTR + 8];
            }
#pragma unroll
            for (int nt = 0; nt < 4; nt++) {
                int kc = (wn * 32 + nt * 8 + g) * QSTR + ks * 16 + tig * 2;
                unsigned bh2[2], bl2[2];
                bh2[0] = *(const unsigned*)&Kh[kc];
                bh2[1] = *(const unsigned*)&Kh[kc + 8];
                bl2[0] = *(const unsigned*)&Kl[kc];
                bl2[1] = *(const unsigned*)&Kl[kc + 8];
#pragma unroll
                for (int mi = 0; mi < 2; mi++) {
                    mma16816(lc[mi][nt], aqh[mi], bh2);
                    mma16816(lc[mi][nt], aqh[mi], bl2);
                    mma16816(lc[mi][nt], aql[mi], bh2);
                }
            }
        }
        // online stats
#pragma unroll
        for (int mi = 0; mi < 2; mi++)
#pragma unroll
            for (int rr = 0; rr < 2; rr++) {
                float tmax = NEG_BIG;
#pragma unroll
                for (int nt = 0; nt < 4; nt++) {
                    tmax = fmaxf(tmax, lc[mi][nt][rr * 2]);
                    tmax = fmaxf(tmax, lc[mi][nt][rr * 2 + 1]);
                }
                tmax = fmaxf(tmax, __shfl_xor_sync(0xffffffffu, tmax, 1));
                tmax = fmaxf(tmax, __shfl_xor_sync(0xffffffffu, tmax, 2));
                int ix = mi * 2 + rr;
                float mold = m_run[ix];
                float mnew = fmaxf(mold, tmax);
                float ps = 0.0f;
#pragma unroll
                for (int nt = 0; nt < 4; nt++) {
                    ps += __expf(lc[mi][nt][rr * 2]     - mnew);
                    ps += __expf(lc[mi][nt][rr * 2 + 1] - mnew);
                }
                ps += __shfl_xor_sync(0xffffffffu, ps, 1);
                ps += __shfl_xor_sync(0xffffffffu, ps, 2);
                s_run[ix] = s_run[ix] * __expf(mold - mnew) + ps;
                m_run[ix] = mnew;
            }
    }

    // merge per-warp partials across wn
    if (tig == 0) {
#pragma unroll
        for (int mi = 0; mi < 2; mi++)
#pragma unroll
            for (int rr = 0; rr < 2; rr++) {
                int r = wm * 32 + mi * 16 + g + rr * 8;
                pbuf[wn * 256 + r * 2]     = m_run[mi * 2 + rr];
                pbuf[wn * 256 + r * 2 + 1] = s_run[mi * 2 + rr];
            }
    }
    __syncthreads();
    if (tid < 128) {
        float m0 = pbuf[tid * 2], s0 = pbuf[tid * 2 + 1];
        float m1 = pbuf[256 + tid * 2], s1 = pbuf[256 + tid * 2 + 1];
        float m = fmaxf(m0, m1);
        float s = s0 * __expf(m0 - m) + s1 * __expf(m1 - m);
        mfin[tid] = m;
        sinv[tid] = 1.0f / s;
    }
    __syncthreads();

    float mrow[2][2], svr[2][2];
#pragma unroll
    for (int mi = 0; mi < 2; mi++)
#pragma unroll
        for (int rr = 0; rr < 2; rr++) {
            int r = wm * 32 + mi * 16 + g + rr * 8;
            mrow[mi][rr] = mfin[r];
            svr[mi][rr] = sinv[r];
        }

    float oacc[2][8][4];
#pragma unroll
    for (int mi = 0; mi < 2; mi++)
#pragma unroll
        for (int nt = 0; nt < 8; nt++)
#pragma unroll
            for (int r = 0; r < 4; r++) oacc[mi][nt][r] = 0.0f;

    // ================= PASS B =================
    for (int t = 0; t < 32; t++) {
        const int k0 = t * 64;
        __syncthreads();
#pragma unroll
        for (int i = 0; i < 4; i++) {
            int e = tid + i * 256, r = e >> 4, c4 = e & 15;
            float4 f = *(const float4*)&Kb[(size_t)(k0 + r) * DEPTH + c4 * 4];
            unsigned h0, l0, h1, l1;
            split_pack2(f.x, f.y, h0, l0);
            split_pack2(f.z, f.w, h1, l1);
            *(unsigned*)&Kh[r * QSTR + c4 * 4]     = h0;
            *(unsigned*)&Kh[r * QSTR + c4 * 4 + 2] = h1;
            *(unsigned*)&Kl[r * QSTR + c4 * 4]     = l0;
            *(unsigned*)&Kl[r * QSTR + c4 * 4 + 2] = l1;
        }
        // V transposed
#pragma unroll
        for (int i = 0; i < 4; i++) {
            int e = tid + i * 256, r = e >> 4, c4 = e & 15;
            float4 f = *(const float4*)&Vb[(size_t)(k0 + r) * DEPTH + c4 * 4];
            float fv[4] = {f.x, f.y, f.z, f.w};
#pragma unroll
            for (int u = 0; u < 4; u++) {
                int d = c4 * 4 + u;
                __nv_bfloat16 hb = __float2bfloat16_rn(fv[u]);
                __nv_bfloat16 lb = __float2bfloat16_rn(fv[u] - __bfloat162float(hb));
                Vh[d * QSTR + r] = hb;
                Vl[d * QSTR + r] = lb;
            }
        }
        __syncthreads();

        float lc[2][4][4];
#pragma unroll
        for (int mi = 0; mi < 2; mi++)
#pragma unroll
            for (int nt = 0; nt < 4; nt++)
#pragma unroll
                for (int r = 0; r < 4; r++) lc[mi][nt][r] = 0.0f;
#pragma unroll
        for (int ks = 0; ks < 4; ks++) {
            unsigned aqh[2][4], aql[2][4];
#pragma unroll
            for (int mi = 0; mi < 2; mi++) {
                int base = (wm * 32 + mi * 16 + g) * QSTR + ks * 16 + tig * 2;
                aqh[mi][0] = *(const unsigned*)&Qh[base];
                aqh[mi][1] = *(const unsigned*)&Qh[base + 8 * QSTR];
                aqh[mi][2] = *(const unsigned*)&Qh[base + 8];
                aqh[mi][3] = *(const unsigned*)&Qh[base + 8 * QSTR + 8];
                aql[mi][0] = *(const unsigned*)&Ql[base];
                aql[mi][1] = *(const unsigned*)&Ql[base + 8 * QSTR];
                aql[mi][2] = *(const unsigned*)&Ql[base + 8];
                aql[mi][3] = *(const unsigned*)&Ql[base + 8 * QSTR + 8];
            }
#pragma unroll
            for (int nt = 0; nt < 4; nt++) {
                int kc = (wn * 32 + nt * 8 + g) * QSTR + ks * 16 + tig * 2;
                unsigned bh2[2], bl2[2];
                bh2[0] = *(const unsigned*)&Kh[kc];
                bh2[1] = *(const unsigned*)&Kh[kc + 8];
                bl2[0] = *(const unsigned*)&Kl[kc];
                bl2[1] = *(const unsigned*)&Kl[kc + 8];
#pragma unroll
                for (int mi = 0; mi < 2; mi++) {
                    mma16816(lc[mi][nt], aqh[mi], bh2);
                    mma16816(lc[mi][nt], aqh[mi], bl2);
                    mma16816(lc[mi][nt], aql[mi], bh2);
                }
            }
        }

        // normalize, write attn, build P fragments, accumulate P@V
        unsigned aPh[2][2][4], aPl[2][2][4];
#pragma unroll
        for (int mi = 0; mi < 2; mi++) {
            int row = q0 + wm * 32 + mi * 16 + g;
#pragma unroll
            for (int nt = 0; nt < 4; nt++) {
                float p0 = __expf(lc[mi][nt][0] - mrow[mi][0]) * svr[mi][0];
                float p1 = __expf(lc[mi][nt][1] - mrow[mi][0]) * svr[mi][0];
                float p2 = __expf(lc[mi][nt][2] - mrow[mi][1]) * svr[mi][1];
                float p3 = __expf(lc[mi][nt][3] - mrow[mi][1]) * svr[mi][1];
                int col = k0 + wn * 32 + nt * 8 + tig * 2;
                *(float2*)&attn[((size_t)bh * Sc + row) * Sc + col] = make_float2(p0, p1);
                *(float2*)&attn[((size_t)bh * Sc + row + 8) * Sc + col] = make_float2(p2, p3);
                unsigned h01, l01, h23, l23;
                split_pack2(p0, p1, h01, l01);
                split_pack2(p2, p3, h23, l23);
                int ks2 = nt >> 1, sl = (nt & 1) * 2;
                aPh[mi][ks2][sl]     = h01;
                aPh[mi][ks2][sl + 1] = h23;
                aPl[mi][ks2][sl]     = l01;
                aPl[mi][ks2][sl + 1] = l23;
            }
        }
#pragma unroll
        for (int ks2 = 0; ks2 < 2; ks2++) {
#pragma unroll
            for (int ntd = 0; ntd < 8; ntd++) {
                // FIX (R8 bug): include this warp's key offset wn*32 so the
                // V B-fragment keys match the P A-fragment keys.
                int dc = (ntd * 8 + g) * QSTR + wn * 32 + ks2 * 16 + tig * 2;
                unsigned bvh[2], bvl[2];
                bvh[0] = *(const unsigned*)&Vh[dc];
                bvh[1] = *(const unsigned*)&Vh[dc + 8];
                bvl[0] = *(const unsigned*)&Vl[dc];
                bvl[1] = *(const unsigned*)&Vl[dc + 8];
#pragma unroll
                for (int mi = 0; mi < 2; mi++) {
                    mma16816(oacc[mi][ntd], aPh[mi][ks2], bvh);
                    mma16816(oacc[mi][ntd], aPh[mi][ks2], bvl);
                    mma16816(oacc[mi][ntd], aPl[mi][ks2], bvh);
                }
            }
        }
    }

    // reduce O across wn pairs, write ctx (merged-head layout)
    __syncthreads();
    if (wn == 1) {
#pragma unroll
        for (int mi = 0; mi < 2; mi++)
#pragma unroll
            for (int ntd = 0; ntd < 8; ntd++) {
                int row = wm * 32 + mi * 16 + g;
                int col = ntd * 8 + tig * 2;
                *(float2*)&obuf[row * 68 + col] =
                    make_float2(oacc[mi][ntd][0], oacc[mi][ntd][1]);
                *(float2*)&obuf[(row + 8) * 68 + col] =
                    make_float2(oacc[mi][ntd][2], oacc[mi][ntd][3]);
            }
    }
    __syncthreads();
    if (wn == 0) {
        const int b = bh >> 4, h = bh & 15;
#pragma unroll
        for (int mi = 0; mi < 2; mi++)
#pragma unroll
            for (int ntd = 0; ntd < 8; ntd++) {
                int row = wm * 32 + mi * 16 + g;
                int col = ntd * 8 + tig * 2;
                float2 o0 = *(float2*)&obuf[row * 68 + col];
                float2 o1 = *(float2*)&obuf[(row + 8) * 68 + col];
                o0.x += oacc[mi][ntd][0]; o0.y += oacc[mi][ntd][1];
                o1.x += oacc[mi][ntd][2]; o1.y += oacc[mi][ntd][3];
                size_t base = ((size_t)(b * Sc + q0 + row)) * DM + h * 64 + col;
                *(float2*)&g_ctx[base] = o0;
                *(float2*)&g_ctx[base + (size_t)8 * DM] = o1;
            }
    }
}

// ---------------------------------------------------------------------------
extern "C" void kernel_launch(void* const* d_in, const int* in_sizes, int n_in,
                              void* d_out, int out_size) {
    const float* v  = (const float*)d_in[0];
    const float* k  = (const float*)d_in[1];
    const float* q  = (const float*)d_in[2];
    const float* wq = (const float*)d_in[3];
    const float* bq = (const float*)d_in[4];
    const float* wk = (const float*)d_in[5];
    const float* bk = (const float*)d_in[6];
    const float* wv = (const float*)d_in[7];
    const float* bv = (const float*)d_in[8];
    const float* wo = (const float*)d_in[9];
    const float* bo = (const float*)d_in[10];

    float* out  = (float*)d_out;
    float* attn = out + (size_t)MROWS * DM;

    const int attn_smem = (128 * QSTR * 2 + 64 * QSTR * 2 + 64 * QSTR * 2) * 2
                          + (128 + 128 + 512) * 4;   // 76800
    cudaFuncSetAttribute(fused_attn, cudaFuncAttributeMaxDynamicSharedMemorySize,
                         attn_smem);

    proj_mma<<<dim3(DM / 128, MROWS / 128, 3), 256>>>(
        q, k, v, wq, wk, wv, bq, bk, bv, wo, bo, out, -1);

    fused_attn<<<dim3(Sc / 128, BH), 256, attn_smem>>>(attn);

    proj_mma<<<dim3(DM / 128, MROWS / 128, 1), 256>>>(
        q, k, v, wq, wk, wv, bq, bk, bv, wo, bo, out, 3);
}

// round 10
// speedup vs baseline: 2.5546x; 1.5473x over previous
#include <cuda_runtime.h>
#include <cuda_bf16.h>

namespace {
constexpr int Bc = 2;
constexpr int Sc = 2048;
constexpr int DM = 1024;
constexpr int Hc = 16;
constexpr int DEPTH = 64;
constexpr int BH = Bc * Hc;
constexpr int MROWS = Bc * Sc;
constexpr float SCALE = 0.125f;
constexpr float NEG_BIG = -3.0e38f;
constexpr int BSTR = 40;     // proj smem stride (bf16)
constexpr int QSTR = 72;     // attention smem stride (bf16)
}

// Packed bf16 hi/lo head tensors (written by proj epilogue)
__device__ __align__(16) unsigned g_qhh[BH * Sc * 32];   // Q*SCALE, pairs along d
__device__ __align__(16) unsigned g_qhl[BH * Sc * 32];
__device__ __align__(16) unsigned g_khh[BH * Sc * 32];
__device__ __align__(16) unsigned g_khl[BH * Sc * 32];
__device__ __align__(16) __nv_bfloat16 g_vth[BH * 64 * Sc];  // V transposed [bh][d][s]
__device__ __align__(16) __nv_bfloat16 g_vtl[BH * 64 * Sc];
__device__ float g_ctx[MROWS * DM];

// ---------------- helpers ----------------
__device__ __forceinline__ void mma16816(float* d, const unsigned* a, const unsigned* b) {
    asm volatile(
        "mma.sync.aligned.m16n8k16.row.col.f32.bf16.bf16.f32 "
        "{%0,%1,%2,%3}, {%4,%5,%6,%7}, {%8,%9}, {%0,%1,%2,%3};"
        : "+f"(d[0]), "+f"(d[1]), "+f"(d[2]), "+f"(d[3])
        : "r"(a[0]), "r"(a[1]), "r"(a[2]), "r"(a[3]), "r"(b[0]), "r"(b[1]));
}
__device__ __forceinline__ void split_pack2(float a, float b, unsigned& hi, unsigned& lo) {
    __nv_bfloat16 ah = __float2bfloat16_rn(a);
    __nv_bfloat16 bh = __float2bfloat16_rn(b);
    __nv_bfloat16 al = __float2bfloat16_rn(a - __bfloat162float(ah));
    __nv_bfloat16 bl = __float2bfloat16_rn(b - __bfloat162float(bh));
    hi = (unsigned)__bfloat16_as_ushort(ah) | ((unsigned)__bfloat16_as_ushort(bh) << 16);
    lo = (unsigned)__bfloat16_as_ushort(al) | ((unsigned)__bfloat16_as_ushort(bl) << 16);
}

// ---------------------------------------------------------------------------
// HMMA projection GEMM. sel 0/1 -> packed hi/lo Q(scaled)/K; sel 2 -> V
// transposed bf16; sel 3 -> g_ctx @ wo + bo -> extout (fp32).
// ---------------------------------------------------------------------------
__global__ __launch_bounds__(256, 2) void proj_mma(
    const float* __restrict__ q, const float* __restrict__ k, const float* __restrict__ v,
    const float* __restrict__ wq, const float* __restrict__ wk, const float* __restrict__ wv,
    const float* __restrict__ bq, const float* __restrict__ bk, const float* __restrict__ bv,
    const float* __restrict__ wo, const float* __restrict__ bo,
    float* __restrict__ extout, int selArg) {
    const int sel = (selArg < 0) ? (int)blockIdx.z : selArg;
    const float* X    = sel == 0 ? q  : sel == 1 ? k  : sel == 2 ? v  : g_ctx;
    const float* W    = sel == 0 ? wq : sel == 1 ? wk : sel == 2 ? wv : wo;
    const float* bias = sel == 0 ? bq : sel == 1 ? bk : sel == 2 ? bv : bo;

    __shared__ __nv_bfloat16 Ah[128][BSTR], Al[128][BSTR];
    __shared__ __nv_bfloat16 Bh[128][BSTR], Bl[128][BSTR];

    const int tid = threadIdx.x;
    const int wid = tid >> 5, lane = tid & 31;
    const int g = lane >> 2, tig = lane & 3;
    const int wm = wid & 3, wn = wid >> 2;
    const int m0 = blockIdx.y * 128, n0 = blockIdx.x * 128;

    float acc[2][8][4];
#pragma unroll
    for (int mi = 0; mi < 2; mi++)
#pragma unroll
        for (int nt = 0; nt < 8; nt++)
#pragma unroll
            for (int r = 0; r < 4; r++) acc[mi][nt][r] = 0.0f;

    const int nloc = tid & 127;
    const int khalf = (tid >> 7) * 16;
    const float* Wcol = W + n0 + nloc;

    for (int k0 = 0; k0 < DM; k0 += 32) {
#pragma unroll
        for (int i = 0; i < 4; i++) {
            int e = tid + i * 256;
            int r = e >> 3, c4 = e & 7;
            float4 f = *(const float4*)&X[(size_t)(m0 + r) * DM + k0 + c4 * 4];
            unsigned h0, l0, h1, l1;
            split_pack2(f.x, f.y, h0, l0);
            split_pack2(f.z, f.w, h1, l1);
            *(unsigned*)&Ah[r][c4 * 4]     = h0;
            *(unsigned*)&Ah[r][c4 * 4 + 2] = h1;
            *(unsigned*)&Al[r][c4 * 4]     = l0;
            *(unsigned*)&Al[r][c4 * 4 + 2] = l1;
        }
#pragma unroll
        for (int kp = 0; kp < 8; kp++) {
            int kk = k0 + khalf + kp * 2;
            float x0 = Wcol[(size_t)kk * DM];
            float x1 = Wcol[(size_t)(kk + 1) * DM];
            unsigned hi, lo;
            split_pack2(x0, x1, hi, lo);
            *(unsigned*)&Bh[nloc][khalf + kp * 2] = hi;
            *(unsigned*)&Bl[nloc][khalf + kp * 2] = lo;
        }
        __syncthreads();

#pragma unroll
        for (int ks = 0; ks < 32; ks += 16) {
            unsigned ah[2][4], al[2][4];
#pragma unroll
            for (int mi = 0; mi < 2; mi++) {
                int r0 = wm * 32 + mi * 16 + g;
                ah[mi][0] = *(const unsigned*)&Ah[r0][ks + tig * 2];
                ah[mi][1] = *(const unsigned*)&Ah[r0 + 8][ks + tig * 2];
                ah[mi][2] = *(const unsigned*)&Ah[r0][ks + tig * 2 + 8];
                ah[mi][3] = *(const unsigned*)&Ah[r0 + 8][ks + tig * 2 + 8];
                al[mi][0] = *(const unsigned*)&Al[r0][ks + tig * 2];
                al[mi][1] = *(const unsigned*)&Al[r0 + 8][ks + tig * 2];
                al[mi][2] = *(const unsigned*)&Al[r0][ks + tig * 2 + 8];
                al[mi][3] = *(const unsigned*)&Al[r0 + 8][ks + tig * 2 + 8];
            }
#pragma unroll
            for (int nt = 0; nt < 8; nt++) {
                int nc = wn * 64 + nt * 8 + g;
                unsigned bh2[2], bl2[2];
                bh2[0] = *(const unsigned*)&Bh[nc][ks + tig * 2];
                bh2[1] = *(const unsigned*)&Bh[nc][ks + tig * 2 + 8];
                bl2[0] = *(const unsigned*)&Bl[nc][ks + tig * 2];
                bl2[1] = *(const unsigned*)&Bl[nc][ks + tig * 2 + 8];
#pragma unroll
                for (int mi = 0; mi < 2; mi++) {
                    mma16816(acc[mi][nt], ah[mi], bh2);
                    mma16816(acc[mi][nt], ah[mi], bl2);
                    mma16816(acc[mi][nt], al[mi], bh2);
                }
            }
        }
        __syncthreads();
    }

#pragma unroll
    for (int mi = 0; mi < 2; mi++) {
        int rbase = m0 + wm * 32 + mi * 16 + g;
#pragma unroll
        for (int nt = 0; nt < 8; nt++) {
            int col0 = n0 + wn * 64 + nt * 8 + tig * 2;
            float bx = bias[col0], by = bias[col0 + 1];
#pragma unroll
            for (int rr = 0; rr < 2; rr++) {
                int row = rbase + rr * 8;
                float v0 = acc[mi][nt][rr * 2]     + bx;
                float v1 = acc[mi][nt][rr * 2 + 1] + by;
                if (sel == 3) {
                    *(float2*)&extout[(size_t)row * DM + col0] = make_float2(v0, v1);
                    continue;
                }
                int hh = col0 >> 6, d = col0 & 63;
                int b = row >> 11, s = row & 2047;
                if (sel == 2) {
                    // V transposed bf16 hi/lo: [bh][d][s]
                    __nv_bfloat16 h0 = __float2bfloat16_rn(v0);
                    __nv_bfloat16 h1 = __float2bfloat16_rn(v1);
                    __nv_bfloat16 l0 = __float2bfloat16_rn(v0 - __bfloat162float(h0));
                    __nv_bfloat16 l1 = __float2bfloat16_rn(v1 - __bfloat162float(h1));
                    size_t base = ((size_t)(b * Hc + hh) * 64 + d) * Sc + s;
                    g_vth[base]      = h0;
                    g_vth[base + Sc] = h1;
                    g_vtl[base]      = l0;
                    g_vtl[base + Sc] = l1;
                } else {
                    if (sel == 0) { v0 *= SCALE; v1 *= SCALE; }
                    unsigned hi, lo;
                    split_pack2(v0, v1, hi, lo);
                    size_t idx = ((size_t)(b * Hc + hh) * Sc + s) * 32 + (d >> 1);
                    if (sel == 0) { g_qhh[idx] = hi; g_qhl[idx] = lo; }
                    else          { g_khh[idx] = hi; g_khl[idx] = lo; }
                }
            }
        }
    }
}

// ---------------------------------------------------------------------------
// Fused HMMA attention (R9 compute, loads are now pure packed copies).
// ---------------------------------------------------------------------------
__global__ __launch_bounds__(256, 2) void fused_attn(float* __restrict__ attn) {
    extern __shared__ char smraw[];
    __nv_bfloat16* Qh = (__nv_bfloat16*)smraw;      // [128][QSTR]
    __nv_bfloat16* Ql = Qh + 128 * QSTR;
    __nv_bfloat16* Kh = Ql + 128 * QSTR;            // [64][QSTR]
    __nv_bfloat16* Kl = Kh + 64 * QSTR;
    __nv_bfloat16* Vh = Kl + 64 * QSTR;             // transposed [d][key]
    __nv_bfloat16* Vl = Vh + 64 * QSTR;
    float* mfin = (float*)(Vl + 64 * QSTR);
    float* sinv = mfin + 128;
    float* pbuf = sinv + 128;                       // [2][128][2]
    float* obuf = (float*)Kh;                       // alias after last sync

    const int bh = blockIdx.y, q0 = blockIdx.x * 128;
    const int tid = threadIdx.x;
    const int wid = tid >> 5, lane = tid & 31;
    const int g = lane >> 2, tig = lane & 3;
    const int wm = wid & 3, wn = wid >> 2;

    const unsigned* Qgh = g_qhh + (size_t)bh * Sc * 32;
    const unsigned* Qgl = g_qhl + (size_t)bh * Sc * 32;
    const unsigned* Kgh = g_khh + (size_t)bh * Sc * 32;
    const unsigned* Kgl = g_khl + (size_t)bh * Sc * 32;
    const __nv_bfloat16* Vgh = g_vth + (size_t)bh * 64 * Sc;
    const __nv_bfloat16* Vgl = g_vtl + (size_t)bh * 64 * Sc;

    // Q tile: pure copy (scale pre-applied)
#pragma unroll
    for (int i = 0; i < 4; i++) {
        int e = tid + i * 256;                  // 1024 uint4 per buffer
        int r = e >> 3, c4 = e & 7;
        *(uint4*)&Qh[r * QSTR + c4 * 8] = *(const uint4*)&Qgh[(size_t)(q0 + r) * 32 + c4 * 4];
        *(uint4*)&Ql[r * QSTR + c4 * 8] = *(const uint4*)&Qgl[(size_t)(q0 + r) * 32 + c4 * 4];
    }

    float m_run[4], s_run[4];
#pragma unroll
    for (int i = 0; i < 4; i++) { m_run[i] = NEG_BIG; s_run[i] = 0.0f; }

    // ================= PASS A =================
    for (int t = 0; t < 32; t++) {
        const int k0 = t * 64;
        __syncthreads();
#pragma unroll
        for (int i = 0; i < 2; i++) {
            int e = tid + i * 256;              // 512 uint4 per buffer
            int r = e >> 3, c4 = e & 7;
            *(uint4*)&Kh[r * QSTR + c4 * 8] = *(const uint4*)&Kgh[(size_t)(k0 + r) * 32 + c4 * 4];
            *(uint4*)&Kl[r * QSTR + c4 * 8] = *(const uint4*)&Kgl[(size_t)(k0 + r) * 32 + c4 * 4];
        }
        __syncthreads();

        float lc[2][4][4];
#pragma unroll
        for (int mi = 0; mi < 2; mi++)
#pragma unroll
            for (int nt = 0; nt < 4; nt++)
#pragma unroll
                for (int r = 0; r < 4; r++) lc[mi][nt][r] = 0.0f;
#pragma unroll
        for (int ks = 0; ks < 4; ks++) {
            unsigned aqh[2][4], aql[2][4];
#pragma unroll
            for (int mi = 0; mi < 2; mi++) {
                int base = (wm * 32 + mi * 16 + g) * QSTR + ks * 16 + tig * 2;
                aqh[mi][0] = *(const unsigned*)&Qh[base];
                aqh[mi][1] = *(const unsigned*)&Qh[base + 8 * QSTR];
                aqh[mi][2] = *(const unsigned*)&Qh[base + 8];
                aqh[mi][3] = *(const unsigned*)&Qh[base + 8 * QSTR + 8];
                aql[mi][0] = *(const unsigned*)&Ql[base];
                aql[mi][1] = *(const unsigned*)&Ql[base + 8 * QSTR];
                aql[mi][2] = *(const unsigned*)&Ql[base + 8];
                aql[mi][3] = *(const unsigned*)&Ql[base + 8 * QSTR + 8];
            }
#pragma unroll
            for (int nt = 0; nt < 4; nt++) {
                int kc = (wn * 32 + nt * 8 + g) * QSTR + ks * 16 + tig * 2;
                unsigned bh2[2], bl2[2];
                bh2[0] = *(const unsigned*)&Kh[kc];
                bh2[1] = *(const unsigned*)&Kh[kc + 8];
                bl2[0] = *(const unsigned*)&Kl[kc];
                bl2[1] = *(const unsigned*)&Kl[kc + 8];
#pragma unroll
                for (int mi = 0; mi < 2; mi++) {
                    mma16816(lc[mi][nt], aqh[mi], bh2);
                    mma16816(lc[mi][nt], aqh[mi], bl2);
                    mma16816(lc[mi][nt], aql[mi], bh2);
                }
            }
        }
#pragma unroll
        for (int mi = 0; mi < 2; mi++)
#pragma unroll
            for (int rr = 0; rr < 2; rr++) {
                float tmax = NEG_BIG;
#pragma unroll
                for (int nt = 0; nt < 4; nt++) {
                    tmax = fmaxf(tmax, lc[mi][nt][rr * 2]);
                    tmax = fmaxf(tmax, lc[mi][nt][rr * 2 + 1]);
                }
                tmax = fmaxf(tmax, __shfl_xor_sync(0xffffffffu, tmax, 1));
                tmax = fmaxf(tmax, __shfl_xor_sync(0xffffffffu, tmax, 2));
                int ix = mi * 2 + rr;
                float mold = m_run[ix];
                float mnew = fmaxf(mold, tmax);
                float ps = 0.0f;
#pragma unroll
                for (int nt = 0; nt < 4; nt++) {
                    ps += __expf(lc[mi][nt][rr * 2]     - mnew);
                    ps += __expf(lc[mi][nt][rr * 2 + 1] - mnew);
                }
                ps += __shfl_xor_sync(0xffffffffu, ps, 1);
                ps += __shfl_xor_sync(0xffffffffu, ps, 2);
                s_run[ix] = s_run[ix] * __expf(mold - mnew) + ps;
                m_run[ix] = mnew;
            }
    }

    // merge per-warp partials across wn
    if (tig == 0) {
#pragma unroll
        for (int mi = 0; mi < 2; mi++)
#pragma unroll
            for (int rr = 0; rr < 2; rr++) {
                int r = wm * 32 + mi * 16 + g + rr * 8;
                pbuf[wn * 256 + r * 2]     = m_run[mi * 2 + rr];
                pbuf[wn * 256 + r * 2 + 1] = s_run[mi * 2 + rr];
            }
    }
    __syncthreads();
    if (tid < 128) {
        float m0 = pbuf[tid * 2], s0 = pbuf[tid * 2 + 1];
        float m1 = pbuf[256 + tid * 2], s1 = pbuf[256 + tid * 2 + 1];
        float m = fmaxf(m0, m1);
        float s = s0 * __expf(m0 - m) + s1 * __expf(m1 - m);
        mfin[tid] = m;
        sinv[tid] = 1.0f / s;
    }
    __syncthreads();

    float mrow[2][2], svr[2][2];
#pragma unroll
    for (int mi = 0; mi < 2; mi++)
#pragma unroll
        for (int rr = 0; rr < 2; rr++) {
            int r = wm * 32 + mi * 16 + g + rr * 8;
            mrow[mi][rr] = mfin[r];
            svr[mi][rr] = sinv[r];
        }

    float oacc[2][8][4];
#pragma unroll
    for (int mi = 0; mi < 2; mi++)
#pragma unroll
        for (int nt = 0; nt < 8; nt++)
#pragma unroll
            for (int r = 0; r < 4; r++) oacc[mi][nt][r] = 0.0f;

    // ================= PASS B =================
    for (int t = 0; t < 32; t++) {
        const int k0 = t * 64;
        __syncthreads();
#pragma unroll
        for (int i = 0; i < 2; i++) {
            int e = tid + i * 256;
            int r = e >> 3, c4 = e & 7;
            *(uint4*)&Kh[r * QSTR + c4 * 8] = *(const uint4*)&Kgh[(size_t)(k0 + r) * 32 + c4 * 4];
            *(uint4*)&Kl[r * QSTR + c4 * 8] = *(const uint4*)&Kgl[(size_t)(k0 + r) * 32 + c4 * 4];
        }
        // V: pure copy from transposed gmem layout
#pragma unroll
        for (int i = 0; i < 2; i++) {
            int e = tid + i * 256;              // 512 uint4 per buffer
            int d = e >> 3, k8 = e & 7;
            *(uint4*)&Vh[d * QSTR + k8 * 8] = *(const uint4*)&Vgh[(size_t)d * Sc + k0 + k8 * 8];
            *(uint4*)&Vl[d * QSTR + k8 * 8] = *(const uint4*)&Vgl[(size_t)d * Sc + k0 + k8 * 8];
        }
        __syncthreads();

        float lc[2][4][4];
#pragma unroll
        for (int mi = 0; mi < 2; mi++)
#pragma unroll
            for (int nt = 0; nt < 4; nt++)
#pragma unroll
                for (int r = 0; r < 4; r++) lc[mi][nt][r] = 0.0f;
#pragma unroll
        for (int ks = 0; ks < 4; ks++) {
            unsigned aqh[2][4], aql[2][4];
#pragma unroll
            for (int mi = 0; mi < 2; mi++) {
                int base = (wm * 32 + mi * 16 + g) * QSTR + ks * 16 + tig * 2;
                aqh[mi][0] = *(const unsigned*)&Qh[base];
                aqh[mi][1] = *(const unsigned*)&Qh[base + 8 * QSTR];
                aqh[mi][2] = *(const unsigned*)&Qh[base + 8];
                aqh[mi][3] = *(const unsigned*)&Qh[base + 8 * QSTR + 8];
                aql[mi][0] = *(const unsigned*)&Ql[base];
                aql[mi][1] = *(const unsigned*)&Ql[base + 8 * QSTR];
                aql[mi][2] = *(const unsigned*)&Ql[base + 8];
                aql[mi][3] = *(const unsigned*)&Ql[base + 8 * QSTR + 8];
            }
#pragma unroll
            for (int nt = 0; nt < 4; nt++) {
                int kc = (wn * 32 + nt * 8 + g) * QSTR + ks * 16 + tig * 2;
                unsigned bh2[2], bl2[2];
                bh2[0] = *(const unsigned*)&Kh[kc];
                bh2[1] = *(const unsigned*)&Kh[kc + 8];
                bl2[0] = *(const unsigned*)&Kl[kc];
                bl2[1] = *(const unsigned*)&Kl[kc + 8];
#pragma unroll
                for (int mi = 0; mi < 2; mi++) {
                    mma16816(lc[mi][nt], aqh[mi], bh2);
                    mma16816(lc[mi][nt], aqh[mi], bl2);
                    mma16816(lc[mi][nt], aql[mi], bh2);
                }
            }
        }

        unsigned aPh[2][2][4], aPl[2][2][4];
#pragma unroll
        for (int mi = 0; mi < 2; mi++) {
            int row = q0 + wm * 32 + mi * 16 + g;
#pragma unroll
            for (int nt = 0; nt < 4; nt++) {
                float p0 = __expf(lc[mi][nt][0] - mrow[mi][0]) * svr[mi][0];
                float p1 = __expf(lc[mi][nt][1] - mrow[mi][0]) * svr[mi][0];
                float p2 = __expf(lc[mi][nt][2] - mrow[mi][1]) * svr[mi][1];
                float p3 = __expf(lc[mi][nt][3] - mrow[mi][1]) * svr[mi][1];
                int col = k0 + wn * 32 + nt * 8 + tig * 2;
                *(float2*)&attn[((size_t)bh * Sc + row) * Sc + col] = make_float2(p0, p1);
                *(float2*)&attn[((size_t)bh * Sc + row + 8) * Sc + col] = make_float2(p2, p3);
                unsigned h01, l01, h23, l23;
                split_pack2(p0, p1, h01, l01);
                split_pack2(p2, p3, h23, l23);
                int ks2 = nt >> 1, sl = (nt & 1) * 2;
                aPh[mi][ks2][sl]     = h01;
                aPh[mi][ks2][sl + 1] = h23;
                aPl[mi][ks2][sl]     = l01;
                aPl[mi][ks2][sl + 1] = l23;
            }
        }
#pragma unroll
        for (int ks2 = 0; ks2 < 2; ks2++) {
#pragma unroll
            for (int ntd = 0; ntd < 8; ntd++) {
                int dc = (ntd * 8 + g) * QSTR + wn * 32 + ks2 * 16 + tig * 2;
                unsigned bvh[2], bvl[2];
                bvh[0] = *(const unsigned*)&Vh[dc];
                bvh[1] = *(const unsigned*)&Vh[dc + 8];
                bvl[0] = *(const unsigned*)&Vl[dc];
                bvl[1] = *(const unsigned*)&Vl[dc + 8];
#pragma unroll
                for (int mi = 0; mi < 2; mi++) {
                    mma16816(oacc[mi][ntd], aPh[mi][ks2], bvh);
                    mma16816(oacc[mi][ntd], aPh[mi][ks2], bvl);
                    mma16816(oacc[mi][ntd], aPl[mi][ks2], bvh);
                }
            }
        }
    }

    // reduce O across wn pairs, write ctx (merged-head layout)
    __syncthreads();
    if (wn == 1) {
#pragma unroll
        for (int mi = 0; mi < 2; mi++)
#pragma unroll
            for (int ntd = 0; ntd < 8; ntd++) {
                int row = wm * 32 + mi * 16 + g;
                int col = ntd * 8 + tig * 2;
                *(float2*)&obuf[row * 68 + col] =
                    make_float2(oacc[mi][ntd][0], oacc[mi][ntd][1]);
                *(float2*)&obuf[(row + 8) * 68 + col] =
                    make_float2(oacc[mi][ntd][2], oacc[mi][ntd][3]);
            }
    }
    __syncthreads();
    if (wn == 0) {
        const int b = bh >> 4, h = bh & 15;
#pragma unroll
        for (int mi = 0; mi < 2; mi++)
#pragma unroll
            for (int ntd = 0; ntd < 8; ntd++) {
                int row = wm * 32 + mi * 16 + g;
                int col = ntd * 8 + tig * 2;
                float2 o0 = *(float2*)&obuf[row * 68 + col];
                float2 o1 = *(float2*)&obuf[(row + 8) * 68 + col];
                o0.x += oacc[mi][ntd][0]; o0.y += oacc[mi][ntd][1];
                o1.x += oacc[mi][ntd][2]; o1.y += oacc[mi][ntd][3];
                size_t base = ((size_t)(b * Sc + q0 + row)) * DM + h * 64 + col;
                *(float2*)&g_ctx[base] = o0;
                *(float2*)&g_ctx[base + (size_t)8 * DM] = o1;
            }
    }
}

// ---------------------------------------------------------------------------
extern "C" void kernel_launch(void* const* d_in, const int* in_sizes, int n_in,
                              void* d_out, int out_size) {
    const float* v  = (const float*)d_in[0];
    const float* k  = (const float*)d_in[1];
    const float* q  = (const float*)d_in[2];
    const float* wq = (const float*)d_in[3];
    const float* bq = (const float*)d_in[4];
    const float* wk = (const float*)d_in[5];
    const float* bk = (const float*)d_in[6];
    const float* wv = (const float*)d_in[7];
    const float* bv = (const float*)d_in[8];
    const float* wo = (const float*)d_in[9];
    const float* bo = (const float*)d_in[10];

    float* out  = (float*)d_out;
    float* attn = out + (size_t)MROWS * DM;

    const int attn_smem = (128 * QSTR * 2 + 64 * QSTR * 2 + 64 * QSTR * 2) * 2
                          + (128 + 128 + 512) * 4;   // 76800
    cudaFuncSetAttribute(fused_attn, cudaFuncAttributeMaxDynamicSharedMemorySize,
                         attn_smem);

    proj_mma<<<dim3(DM / 128, MROWS / 128, 3), 256>>>(
        q, k, v, wq, wk, wv, bq, bk, bv, wo, bo, out, -1);

    fused_attn<<<dim3(Sc / 128, BH), 256, attn_smem>>>(attn);

    proj_mma<<<dim3(DM / 128, MROWS / 128, 1), 256>>>(
        q, k, v, wq, wk, wv, bq, bk, bv, wo, bo, out, 3);
}

// round 11
// speedup vs baseline: 2.6543x; 1.0390x over previous
#include <cuda_runtime.h>
#include <cuda_bf16.h>

namespace {
constexpr int Bc = 2;
constexpr int Sc = 2048;
constexpr int DM = 1024;
constexpr int Hc = 16;
constexpr int BH = Bc * Hc;
constexpr int MROWS = Bc * Sc;
constexpr float SCALE = 0.125f;
constexpr float NEG_BIG = -3.0e38f;
constexpr int BSTR = 40;     // proj smem stride (bf16)
constexpr int QSTR = 72;     // attention smem stride (bf16)
}

// Pre-converted packed bf16 hi/lo buffers
__device__ __align__(16) unsigned g_xh[3][MROWS * 512];   // inputs, A-layout
__device__ __align__(16) unsigned g_xl[3][MROWS * 512];
__device__ __align__(16) unsigned g_wh[4][DM * 512];      // weights, B-layout [n][k/2]
__device__ __align__(16) unsigned g_wl[4][DM * 512];
__device__ __align__(16) unsigned g_qhh[BH * Sc * 32];    // Q*SCALE head-split
__device__ __align__(16) unsigned g_qhl[BH * Sc * 32];
__device__ __align__(16) unsigned g_khh[BH * Sc * 32];
__device__ __align__(16) unsigned g_khl[BH * Sc * 32];
__device__ __align__(16) __nv_bfloat16 g_vth[BH * 64 * Sc];  // V transposed [bh][d][s]
__device__ __align__(16) __nv_bfloat16 g_vtl[BH * 64 * Sc];
__device__ __align__(16) unsigned g_ch[MROWS * 512];      // ctx packed, A-layout
__device__ __align__(16) unsigned g_cl[MROWS * 512];

// ---------------- helpers ----------------
__device__ __forceinline__ void mma16816(float* d, const unsigned* a, const unsigned* b) {
    asm volatile(
        "mma.sync.aligned.m16n8k16.row.col.f32.bf16.bf16.f32 "
        "{%0,%1,%2,%3}, {%4,%5,%6,%7}, {%8,%9}, {%0,%1,%2,%3};"
        : "+f"(d[0]), "+f"(d[1]), "+f"(d[2]), "+f"(d[3])
        : "r"(a[0]), "r"(a[1]), "r"(a[2]), "r"(a[3]), "r"(b[0]), "r"(b[1]));
}
__device__ __forceinline__ void split_pack2(float a, float b, unsigned& hi, unsigned& lo) {
    __nv_bfloat16 ah = __float2bfloat16_rn(a);
    __nv_bfloat16 bh = __float2bfloat16_rn(b);
    __nv_bfloat16 al = __float2bfloat16_rn(a - __bfloat162float(ah));
    __nv_bfloat16 bl = __float2bfloat16_rn(b - __bfloat162float(bh));
    hi = (unsigned)__bfloat16_as_ushort(ah) | ((unsigned)__bfloat16_as_ushort(bh) << 16);
    lo = (unsigned)__bfloat16_as_ushort(al) | ((unsigned)__bfloat16_as_ushort(bl) << 16);
}
__device__ __forceinline__ unsigned scvta(const void* p) {
    return (unsigned)__cvta_generic_to_shared(p);
}
__device__ __forceinline__ void ldsm4(unsigned* r, unsigned a) {
    asm volatile("ldmatrix.sync.aligned.m8n8.x4.shared.b16 {%0,%1,%2,%3}, [%4];"
                 : "=r"(r[0]), "=r"(r[1]), "=r"(r[2]), "=r"(r[3]) : "r"(a));
}

// ---------------------------------------------------------------------------
// One-time converts
// ---------------------------------------------------------------------------
__global__ __launch_bounds__(256) void conv_x(const float* __restrict__ q,
                                              const float* __restrict__ k,
                                              const float* __restrict__ v) {
    size_t idx = (size_t)blockIdx.x * 256 + threadIdx.x;   // 3 * 2^21
    int sel = (int)(idx >> 21);
    size_t r = idx & ((1u << 21) - 1);
    const float* X = sel == 0 ? q : sel == 1 ? k : v;
    float2 xv = *(const float2*)&X[2 * r];
    unsigned hi, lo;
    split_pack2(xv.x, xv.y, hi, lo);
    g_xh[sel][r] = hi;
    g_xl[sel][r] = lo;
}

__global__ __launch_bounds__(256) void conv_w(const float* __restrict__ wq,
                                              const float* __restrict__ wk,
                                              const float* __restrict__ wv,
                                              const float* __restrict__ wo) {
    const int z = blockIdx.z;
    const float* W = z == 0 ? wq : z == 1 ? wk : z == 2 ? wv : wo;
    __shared__ float t[32][33];
    const int tid = threadIdx.x, tx = tid & 31, ty = tid >> 5;
    const int k0 = blockIdx.y * 32, n0 = blockIdx.x * 32;
#pragma unroll
    for (int i = 0; i < 4; i++)
        t[ty + i * 8][tx] = W[(size_t)(k0 + ty + i * 8) * DM + n0 + tx];
    __syncthreads();
#pragma unroll
    for (int i = 0; i < 2; i++) {
        int e = tid + i * 256, n = e >> 4, c = e & 15;
        unsigned hi, lo;
        split_pack2(t[2 * c][n], t[2 * c + 1][n], hi, lo);
        size_t o = (size_t)(n0 + n) * 512 + (k0 >> 1) + c;
        g_wh[z][o] = hi;
        g_wl[z][o] = lo;
    }
}

// ---------------------------------------------------------------------------
// HMMA projection GEMM (pure-copy fills + ldmatrix fragments).
// sel 0/1 -> packed Q(scaled)/K head tensors; sel 2 -> V transposed bf16;
// sel 3 -> ctx @ wo + bo -> extout fp32.
// ---------------------------------------------------------------------------
__global__ __launch_bounds__(256, 2) void proj_mma(
    const float* __restrict__ bq, const float* __restrict__ bk,
    const float* __restrict__ bv, const float* __restrict__ bo,
    float* __restrict__ extout, int selArg) {
    const int sel = (selArg < 0) ? (int)blockIdx.z : selArg;
    const unsigned* Aph = (sel < 3) ? g_xh[sel] : g_ch;
    const unsigned* Apl = (sel < 3) ? g_xl[sel] : g_cl;
    const unsigned* Bph = g_wh[sel];
    const unsigned* Bpl = g_wl[sel];
    const float* bias = sel == 0 ? bq : sel == 1 ? bk : sel == 2 ? bv : bo;

    __shared__ __nv_bfloat16 Ah[128][BSTR], Al[128][BSTR];
    __shared__ __nv_bfloat16 Bh[128][BSTR], Bl[128][BSTR];

    const int tid = threadIdx.x;
    const int wid = tid >> 5, lane = tid & 31;
    const int g = lane >> 2, tig = lane & 3;
    const int wm = wid & 3, wn = wid >> 2;
    const int m0 = blockIdx.y * 128, n0 = blockIdx.x * 128;
    const int l7 = lane & 7, b8 = (lane >> 3) & 1, b16 = (lane >> 4) & 1;

    const unsigned aAh = scvta(&Ah[wm * 32 + l7 + b8 * 8][b16 * 8]);
    const unsigned aAl = scvta(&Al[wm * 32 + l7 + b8 * 8][b16 * 8]);
    const unsigned aBh = scvta(&Bh[wn * 64 + l7 + b16 * 8][b8 * 8]);
    const unsigned aBl = scvta(&Bl[wn * 64 + l7 + b16 * 8][b8 * 8]);

    float acc[2][8][4];
#pragma unroll
    for (int mi = 0; mi < 2; mi++)
#pragma unroll
        for (int nt = 0; nt < 8; nt++)
#pragma unroll
            for (int r = 0; r < 4; r++) acc[mi][nt][r] = 0.0f;

    for (int k0 = 0; k0 < DM; k0 += 32) {
        const int kp = k0 >> 1;
#pragma unroll
        for (int i = 0; i < 2; i++) {
            int e = tid + i * 256, r = e >> 2, c = e & 3;
            *(uint4*)&Ah[r][c * 8] = *(const uint4*)&Aph[(size_t)(m0 + r) * 512 + kp + c * 4];
            *(uint4*)&Al[r][c * 8] = *(const uint4*)&Apl[(size_t)(m0 + r) * 512 + kp + c * 4];
            *(uint4*)&Bh[r][c * 8] = *(const uint4*)&Bph[(size_t)(n0 + r) * 512 + kp + c * 4];
            *(uint4*)&Bl[r][c * 8] = *(const uint4*)&Bpl[(size_t)(n0 + r) * 512 + kp + c * 4];
        }
        __syncthreads();
#pragma unroll
        for (int ks = 0; ks < 2; ks++) {
            unsigned ah[2][4], al[2][4];
            ldsm4(ah[0], aAh + ks * 32);
            ldsm4(ah[1], aAh + 1280 + ks * 32);
            ldsm4(al[0], aAl + ks * 32);
            ldsm4(al[1], aAl + 1280 + ks * 32);
#pragma unroll
            for (int np = 0; np < 4; np++) {
                unsigned b4h[4], b4l[4];
                ldsm4(b4h, aBh + np * 1280 + ks * 32);
                ldsm4(b4l, aBl + np * 1280 + ks * 32);
#pragma unroll
                for (int j = 0; j < 2; j++) {
                    int nt = np * 2 + j;
#pragma unroll
                    for (int mi = 0; mi < 2; mi++) {
                        mma16816(acc[mi][nt], ah[mi], b4h + 2 * j);
                        mma16816(acc[mi][nt], ah[mi], b4l + 2 * j);
                        mma16816(acc[mi][nt], al[mi], b4h + 2 * j);
                    }
                }
            }
        }
        __syncthreads();
    }

#pragma unroll
    for (int mi = 0; mi < 2; mi++) {
        int rbase = m0 + wm * 32 + mi * 16 + g;
#pragma unroll
        for (int nt = 0; nt < 8; nt++) {
            int col0 = n0 + wn * 64 + nt * 8 + tig * 2;
            float bx = bias[col0], by = bias[col0 + 1];
#pragma unroll
            for (int rr = 0; rr < 2; rr++) {
                int row = rbase + rr * 8;
                float v0 = acc[mi][nt][rr * 2]     + bx;
                float v1 = acc[mi][nt][rr * 2 + 1] + by;
                if (sel == 3) {
                    *(float2*)&extout[(size_t)row * DM + col0] = make_float2(v0, v1);
                    continue;
                }
                int hh = col0 >> 6, d = col0 & 63;
                int b = row >> 11, s = row & 2047;
                if (sel == 2) {
                    __nv_bfloat16 h0 = __float2bfloat16_rn(v0);
                    __nv_bfloat16 h1 = __float2bfloat16_rn(v1);
                    __nv_bfloat16 l0 = __float2bfloat16_rn(v0 - __bfloat162float(h0));
                    __nv_bfloat16 l1 = __float2bfloat16_rn(v1 - __bfloat162float(h1));
                    size_t base = ((size_t)(b * Hc + hh) * 64 + d) * Sc + s;
                    g_vth[base]      = h0;
                    g_vth[base + Sc] = h1;
                    g_vtl[base]      = l0;
                    g_vtl[base + Sc] = l1;
                } else {
                    if (sel == 0) { v0 *= SCALE; v1 *= SCALE; }
                    unsigned hi, lo;
                    split_pack2(v0, v1, hi, lo);
                    size_t idx = ((size_t)(b * Hc + hh) * Sc + s) * 32 + (d >> 1);
                    if (sel == 0) { g_qhh[idx] = hi; g_qhl[idx] = lo; }
                    else          { g_khh[idx] = hi; g_khl[idx] = lo; }
                }
            }
        }
    }
}

// ---------------------------------------------------------------------------
// Fused HMMA attention, ldmatrix fragments, packed ctx output.
// ---------------------------------------------------------------------------
__global__ __launch_bounds__(256, 2) void fused_attn(float* __restrict__ attn) {
    extern __shared__ char smraw[];
    __nv_bfloat16* Qh = (__nv_bfloat16*)smraw;      // [128][QSTR]
    __nv_bfloat16* Ql = Qh + 128 * QSTR;
    __nv_bfloat16* Kh = Ql + 128 * QSTR;            // [64][QSTR]
    __nv_bfloat16* Kl = Kh + 64 * QSTR;
    __nv_bfloat16* Vh = Kl + 64 * QSTR;             // [d][key]
    __nv_bfloat16* Vl = Vh + 64 * QSTR;
    float* mfin = (float*)(Vl + 64 * QSTR);
    float* sinv = mfin + 128;
    float* pbuf = sinv + 128;
    float* obuf = (float*)Kh;                       // alias after last sync

    const int bh = blockIdx.y, q0 = blockIdx.x * 128;
    const int tid = threadIdx.x;
    const int wid = tid >> 5, lane = tid & 31;
    const int g = lane >> 2, tig = lane & 3;
    const int wm = wid & 3, wn = wid >> 2;
    const int l7 = lane & 7, b8 = (lane >> 3) & 1, b16 = (lane >> 4) & 1;

    const unsigned* Qgh = g_qhh + (size_t)bh * Sc * 32;
    const unsigned* Qgl = g_qhl + (size_t)bh * Sc * 32;
    const unsigned* Kgh = g_khh + (size_t)bh * Sc * 32;
    const unsigned* Kgl = g_khl + (size_t)bh * Sc * 32;
    const __nv_bfloat16* Vgh = g_vth + (size_t)bh * 64 * Sc;
    const __nv_bfloat16* Vgl = g_vtl + (size_t)bh * 64 * Sc;

    const unsigned aQh = scvta(&Qh[(wm * 32 + l7 + b8 * 8) * QSTR + b16 * 8]);
    const unsigned aQl = scvta(&Ql[(wm * 32 + l7 + b8 * 8) * QSTR + b16 * 8]);
    const unsigned aKh = scvta(&Kh[(wn * 32 + l7 + b16 * 8) * QSTR + b8 * 8]);
    const unsigned aKl = scvta(&Kl[(wn * 32 + l7 + b16 * 8) * QSTR + b8 * 8]);
    const unsigned aVh = scvta(&Vh[(l7 + b16 * 8) * QSTR + wn * 32 + b8 * 8]);
    const unsigned aVl = scvta(&Vl[(l7 + b16 * 8) * QSTR + wn * 32 + b8 * 8]);

#pragma unroll
    for (int i = 0; i < 4; i++) {
        int e = tid + i * 256, r = e >> 3, c4 = e & 7;
        *(uint4*)&Qh[r * QSTR + c4 * 8] = *(const uint4*)&Qgh[(size_t)(q0 + r) * 32 + c4 * 4];
        *(uint4*)&Ql[r * QSTR + c4 * 8] = *(const uint4*)&Qgl[(size_t)(q0 + r) * 32 + c4 * 4];
    }

    float m_run[4], s_run[4];
#pragma unroll
    for (int i = 0; i < 4; i++) { m_run[i] = NEG_BIG; s_run[i] = 0.0f; }

    // ================= PASS A =================
    for (int t = 0; t < 32; t++) {
        const int k0 = t * 64;
        __syncthreads();
#pragma unroll
        for (int i = 0; i < 2; i++) {
            int e = tid + i * 256, r = e >> 3, c4 = e & 7;
            *(uint4*)&Kh[r * QSTR + c4 * 8] = *(const uint4*)&Kgh[(size_t)(k0 + r) * 32 + c4 * 4];
            *(uint4*)&Kl[r * QSTR + c4 * 8] = *(const uint4*)&Kgl[(size_t)(k0 + r) * 32 + c4 * 4];
        }
        __syncthreads();

        float lc[2][4][4];
#pragma unroll
        for (int mi = 0; mi < 2; mi++)
#pragma unroll
            for (int nt = 0; nt < 4; nt++)
#pragma unroll
                for (int r = 0; r < 4; r++) lc[mi][nt][r] = 0.0f;
#pragma unroll
        for (int ks = 0; ks < 4; ks++) {
            unsigned ah[2][4], al[2][4];
            ldsm4(ah[0], aQh + ks * 32);
            ldsm4(ah[1], aQh + 2304 + ks * 32);
            ldsm4(al[0], aQl + ks * 32);
            ldsm4(al[1], aQl + 2304 + ks * 32);
#pragma unroll
            for (int np = 0; np < 2; np++) {
                unsigned b4h[4], b4l[4];
                ldsm4(b4h, aKh + np * 2304 + ks * 32);
                ldsm4(b4l, aKl + np * 2304 + ks * 32);
#pragma unroll
                for (int j = 0; j < 2; j++) {
                    int nt = np * 2 + j;
#pragma unroll
                    for (int mi = 0; mi < 2; mi++) {
                        mma16816(lc[mi][nt], ah[mi], b4h + 2 * j);
                        mma16816(lc[mi][nt], ah[mi], b4l + 2 * j);
                        mma16816(lc[mi][nt], al[mi], b4h + 2 * j);
                    }
                }
            }
        }
#pragma unroll
        for (int mi = 0; mi < 2; mi++)
#pragma unroll
            for (int rr = 0; rr < 2; rr++) {
                float tmax = NEG_BIG;
#pragma unroll
                for (int nt = 0; nt < 4; nt++) {
                    tmax = fmaxf(tmax, lc[mi][nt][rr * 2]);
                    tmax = fmaxf(tmax, lc[mi][nt][rr * 2 + 1]);
                }
                tmax = fmaxf(tmax, __shfl_xor_sync(0xffffffffu, tmax, 1));
                tmax = fmaxf(tmax, __shfl_xor_sync(0xffffffffu, tmax, 2));
                int ix = mi * 2 + rr;
                float mold = m_run[ix];
                float mnew = fmaxf(mold, tmax);
                float ps = 0.0f;
#pragma unroll
                for (int nt = 0; nt < 4; nt++) {
                    ps += __expf(lc[mi][nt][rr * 2]     - mnew);
                    ps += __expf(lc[mi][nt][rr * 2 + 1] - mnew);
                }
                ps += __shfl_xor_sync(0xffffffffu, ps, 1);
                ps += __shfl_xor_sync(0xffffffffu, ps, 2);
                s_run[ix] = s_run[ix] * __expf(mold - mnew) + ps;
                m_run[ix] = mnew;
            }
    }

    if (tig == 0) {
#pragma unroll
        for (int mi = 0; mi < 2; mi++)
#pragma unroll
            for (int rr = 0; rr < 2; rr++) {
                int r = wm * 32 + mi * 16 + g + rr * 8;
                pbuf[wn * 256 + r * 2]     = m_run[mi * 2 + rr];
                pbuf[wn * 256 + r * 2 + 1] = s_run[mi * 2 + rr];
            }
    }
    __syncthreads();
    if (tid < 128) {
        float m0 = pbuf[tid * 2], s0 = pbuf[tid * 2 + 1];
        float m1 = pbuf[256 + tid * 2], s1 = pbuf[256 + tid * 2 + 1];
        float m = fmaxf(m0, m1);
        float s = s0 * __expf(m0 - m) + s1 * __expf(m1 - m);
        mfin[tid] = m;
        sinv[tid] = 1.0f / s;
    }
    __syncthreads();

    float mrow[2][2], svr[2][2];
#pragma unroll
    for (int mi = 0; mi < 2; mi++)
#pragma unroll
        for (int rr = 0; rr < 2; rr++) {
            int r = wm * 32 + mi * 16 + g + rr * 8;
            mrow[mi][rr] = mfin[r];
            svr[mi][rr] = sinv[r];
        }

    float oacc[2][8][4];
#pragma unroll
    for (int mi = 0; mi < 2; mi++)
#pragma unroll
        for (int nt = 0; nt < 8; nt++)
#pragma unroll
            for (int r = 0; r < 4; r++) oacc[mi][nt][r] = 0.0f;

    // ================= PASS B =================
    for (int t = 0; t < 32; t++) {
        const int k0 = t * 64;
        __syncthreads();
#pragma unroll
        for (int i = 0; i < 2; i++) {
            int e = tid + i * 256, r = e >> 3, c4 = e & 7;
            *(uint4*)&Kh[r * QSTR + c4 * 8] = *(const uint4*)&Kgh[(size_t)(k0 + r) * 32 + c4 * 4];
            *(uint4*)&Kl[r * QSTR + c4 * 8] = *(const uint4*)&Kgl[(size_t)(k0 + r) * 32 + c4 * 4];
        }
#pragma unroll
        for (int i = 0; i < 2; i++) {
            int e = tid + i * 256, d = e >> 3, k8 = e & 7;
            *(uint4*)&Vh[d * QSTR + k8 * 8] = *(const uint4*)&Vgh[(size_t)d * Sc + k0 + k8 * 8];
            *(uint4*)&Vl[d * QSTR + k8 * 8] = *(const uint4*)&Vgl[(size_t)d * Sc + k0 + k8 * 8];
        }
        __syncthreads();

        float lc[2][4][4];
#pragma unroll
        for (int mi = 0; mi < 2; mi++)
#pragma unroll
            for (int nt = 0; nt < 4; nt++)
#pragma unroll
                for (int r = 0; r < 4; r++) lc[mi][nt][r] = 0.0f;
#pragma unroll
        for (int ks = 0; ks < 4; ks++) {
            unsigned ah[2][4], al[2][4];
            ldsm4(ah[0], aQh + ks * 32);
            ldsm4(ah[1], aQh + 2304 + ks * 32);
            ldsm4(al[0], aQl + ks * 32);
            ldsm4(al[1], aQl + 2304 + ks * 32);
#pragma unroll
            for (int np = 0; np < 2; np++) {
                unsigned b4h[4], b4l[4];
                ldsm4(b4h, aKh + np * 2304 + ks * 32);
                ldsm4(b4l, aKl + np * 2304 + ks * 32);
#pragma unroll
                for (int j = 0; j < 2; j++) {
                    int nt = np * 2 + j;
#pragma unroll
                    for (int mi = 0; mi < 2; mi++) {
                        mma16816(lc[mi][nt], ah[mi], b4h + 2 * j);
                        mma16816(lc[mi][nt], ah[mi], b4l + 2 * j);
                        mma16816(lc[mi][nt], al[mi], b4h + 2 * j);
                    }
                }
            }
        }

        unsigned aPh[2][2][4], aPl[2][2][4];
#pragma unroll
        for (int mi = 0; mi < 2; mi++) {
            int row = q0 + wm * 32 + mi * 16 + g;
#pragma unroll
            for (int nt = 0; nt < 4; nt++) {
                float p0 = __expf(lc[mi][nt][0] - mrow[mi][0]) * svr[mi][0];
                float p1 = __expf(lc[mi][nt][1] - mrow[mi][0]) * svr[mi][0];
                float p2 = __expf(lc[mi][nt][2] - mrow[mi][1]) * svr[mi][1];
                float p3 = __expf(lc[mi][nt][3] - mrow[mi][1]) * svr[mi][1];
                int col = k0 + wn * 32 + nt * 8 + tig * 2;
                *(float2*)&attn[((size_t)bh * Sc + row) * Sc + col] = make_float2(p0, p1);
                *(float2*)&attn[((size_t)bh * Sc + row + 8) * Sc + col] = make_float2(p2, p3);
                unsigned h01, l01, h23, l23;
                split_pack2(p0, p1, h01, l01);
                split_pack2(p2, p3, h23, l23);
                int ks2 = nt >> 1, sl = (nt & 1) * 2;
                aPh[mi][ks2][sl]     = h01;
                aPh[mi][ks2][sl + 1] = h23;
                aPl[mi][ks2][sl]     = l01;
                aPl[mi][ks2][sl + 1] = l23;
            }
        }
#pragma unroll
        for (int ks2 = 0; ks2 < 2; ks2++) {
#pragma unroll
            for (int ndp = 0; ndp < 4; ndp++) {
                unsigned b4h[4], b4l[4];
                ldsm4(b4h, aVh + ndp * 2304 + ks2 * 32);
                ldsm4(b4l, aVl + ndp * 2304 + ks2 * 32);
#pragma unroll
                for (int j = 0; j < 2; j++) {
                    int ntd = ndp * 2 + j;
#pragma unroll
                    for (int mi = 0; mi < 2; mi++) {
                        mma16816(oacc[mi][ntd], aPh[mi][ks2], b4h + 2 * j);
                        mma16816(oacc[mi][ntd], aPh[mi][ks2], b4l + 2 * j);
                        mma16816(oacc[mi][ntd], aPl[mi][ks2], b4h + 2 * j);
                    }
                }
            }
        }
    }

    // reduce O across wn, write ctx packed hi/lo
    __syncthreads();
    if (wn == 1) {
#pragma unroll
        for (int mi = 0; mi < 2; mi++)
#pragma unroll
            for (int ntd = 0; ntd < 8; ntd++) {
                int row = wm * 32 + mi * 16 + g;
                int col = ntd * 8 + tig * 2;
                *(float2*)&obuf[row * 68 + col] =
                    make_float2(oacc[mi][ntd][0], oacc[mi][ntd][1]);
                *(float2*)&obuf[(row + 8) * 68 + col] =
                    make_float2(oacc[mi][ntd][2], oacc[mi][ntd][3]);
            }
    }
    __syncthreads();
    if (wn == 0) {
        const int b = bh >> 4, h = bh & 15;
#pragma unroll
        for (int mi = 0; mi < 2; mi++)
#pragma unroll
            for (int ntd = 0; ntd < 8; ntd++) {
                int row = wm * 32 + mi * 16 + g;
                int col = ntd * 8 + tig * 2;
                float2 o0 = *(float2*)&obuf[row * 68 + col];
                float2 o1 = *(float2*)&obuf[(row + 8) * 68 + col];
                o0.x += oacc[mi][ntd][0]; o0.y += oacc[mi][ntd][1];
                o1.x += oacc[mi][ntd][2]; o1.y += oacc[mi][ntd][3];
                unsigned hi, lo;
                size_t base = ((size_t)(b * Sc + q0 + row)) * 512 + ((h * 64 + col) >> 1);
                split_pack2(o0.x, o0.y, hi, lo);
                g_ch[base] = hi; g_cl[base] = lo;
                size_t base8 = base + (size_t)8 * 512;
                split_pack2(o1.x, o1.y, hi, lo);
                g_ch[base8] = hi; g_cl[base8] = lo;
            }
    }
}

// ---------------------------------------------------------------------------
extern "C" void kernel_launch(void* const* d_in, const int* in_sizes, int n_in,
                              void* d_out, int out_size) {
    const float* v  = (const float*)d_in[0];
    const float* k  = (const float*)d_in[1];
    const float* q  = (const float*)d_in[2];
    const float* wq = (const float*)d_in[3];
    const float* bq = (const float*)d_in[4];
    const float* wk = (const float*)d_in[5];
    const float* bk = (const float*)d_in[6];
    const float* wv = (const float*)d_in[7];
    const float* bv = (const float*)d_in[8];
    const float* wo = (const float*)d_in[9];
    const float* bo = (const float*)d_in[10];

    float* out  = (float*)d_out;
    float* attn = out + (size_t)MROWS * DM;

    const int attn_smem = (128 * QSTR * 2 + 64 * QSTR * 2 + 64 * QSTR * 2) * 2
                          + (128 + 128 + 512) * 4;   // 76800
    cudaFuncSetAttribute(fused_attn, cudaFuncAttributeMaxDynamicSharedMemorySize,
                         attn_smem);

    conv_x<<<3 * (MROWS * 512) / 256, 256>>>(q, k, v);
    conv_w<<<dim3(32, 32, 4), 256>>>(wq, wk, wv, wo);

    proj_mma<<<dim3(DM / 128, MROWS / 128, 3), 256>>>(bq, bk, bv, bo, out, -1);

    fused_attn<<<dim3(Sc / 128, BH), 256, attn_smem>>>(attn);

    proj_mma<<<dim3(DM / 128, MROWS / 128, 1), 256>>>(bq, bk, bv, bo, out, 3);
}